// round 1
// baseline (speedup 1.0000x reference)
#include <cuda_runtime.h>
#include <math.h>

// Problem constants
#define D_EMB   512
#define H_NUM   8
#define T_STEPS 16
#define NB      2
#define SEQ     512
#define HD      64
#define M_ROWS  (NB * T_STEPS * SEQ)      // 16384
#define PBATCH  (NB * T_STEPS * H_NUM)    // 256

// ---- scratch (device globals; no runtime allocation allowed) ----
__device__ float g_Q[(size_t)M_ROWS * D_EMB];
__device__ float g_K[(size_t)M_ROWS * D_EMB];
__device__ float g_V[(size_t)M_ROWS * D_EMB];
__device__ float g_att[(size_t)M_ROWS * D_EMB];
__device__ float g_scores[(size_t)PBATCH * SEQ * SEQ];   // 256 MB

// ============================================================================
// Kernel 1/5: projection GEMM  C[M,512] = A[M,512] @ W[512,512] + bias
// 128x128 block tile, BK=8, 8x8 per-thread microtile (split 4+4 fragments).
// grid = (N/128=4, M/128), block = 256
// ============================================================================
__global__ __launch_bounds__(256) void proj_gemm(
    const float* __restrict__ A, const float* __restrict__ W,
    const float* __restrict__ bias, float* __restrict__ C)
{
    __shared__ float As[8][128];
    __shared__ float Ws[8][128];
    const int tid = threadIdx.x;
    const int tx = tid & 15, ty = tid >> 4;
    const int rowBlk = blockIdx.y * 128;
    const int colBlk = blockIdx.x * 128;
    const int aRow = tid >> 1, aCol = (tid & 1) * 4;
    const int wRow = tid >> 5, wCol = (tid & 31) * 4;

    float acc[8][8] = {};
    for (int k0 = 0; k0 < 512; k0 += 8) {
        float4 av = *(const float4*)(A + (size_t)(rowBlk + aRow) * 512 + k0 + aCol);
        As[aCol + 0][aRow] = av.x; As[aCol + 1][aRow] = av.y;
        As[aCol + 2][aRow] = av.z; As[aCol + 3][aRow] = av.w;
        *(float4*)&Ws[wRow][wCol] =
            *(const float4*)(W + (size_t)(k0 + wRow) * 512 + colBlk + wCol);
        __syncthreads();
#pragma unroll
        for (int kk = 0; kk < 8; kk++) {
            float a[8], b[8];
            *(float4*)(a)     = *(const float4*)&As[kk][ty * 4];
            *(float4*)(a + 4) = *(const float4*)&As[kk][64 + ty * 4];
            *(float4*)(b)     = *(const float4*)&Ws[kk][tx * 4];
            *(float4*)(b + 4) = *(const float4*)&Ws[kk][64 + tx * 4];
#pragma unroll
            for (int i = 0; i < 8; i++)
#pragma unroll
                for (int j = 0; j < 8; j++) acc[i][j] += a[i] * b[j];
        }
        __syncthreads();
    }
#pragma unroll
    for (int ih = 0; ih < 2; ih++)
#pragma unroll
        for (int i = 0; i < 4; i++) {
            const int r = rowBlk + ih * 64 + ty * 4 + i;
#pragma unroll
            for (int jh = 0; jh < 2; jh++) {
                const int c = colBlk + jh * 64 + tx * 4;
                float4 v;
                v.x = acc[ih * 4 + i][jh * 4 + 0] + bias[c + 0];
                v.y = acc[ih * 4 + i][jh * 4 + 1] + bias[c + 1];
                v.z = acc[ih * 4 + i][jh * 4 + 2] + bias[c + 2];
                v.w = acc[ih * 4 + i][jh * 4 + 3] + bias[c + 3];
                *(float4*)(C + (size_t)r * 512 + c) = v;
            }
        }
}

// ============================================================================
// Kernel 2/5: batched scores  S[p, q, k] = (Q.Kdot/8)*modw[h] + sync[t,h]
// Per batch p = (b,t,h): Q,K are 512x64 with row stride 512.
// grid = (4, 4, 256), block = 256. NT GEMM, Kdim = 64.
// ============================================================================
__global__ __launch_bounds__(256) void scores_gemm(
    const float* __restrict__ mw, const float* __restrict__ tsync,
    const int* __restrict__ qm, const int* __restrict__ km)
{
    const int p = blockIdx.z;
    const int h = p & 7;
    const int t = (p >> 3) & 15;
    const int b = p >> 7;
    const size_t base = ((size_t)(b * T_STEPS + t) * SEQ) * 512 + h * HD;
    const float* Q = g_Q + base;
    const float* K = g_K + base;
    float* S = g_scores + (size_t)p * SEQ * SEQ;

    __shared__ float Qs[8][128];
    __shared__ float Ks[8][128];
    const int tid = threadIdx.x;
    const int tx = tid & 15, ty = tid >> 4;
    const int rowBlk = blockIdx.y * 128;
    const int colBlk = blockIdx.x * 128;
    const int aRow = tid >> 1, aCol = (tid & 1) * 4;

    float acc[8][8] = {};
    for (int k0 = 0; k0 < HD; k0 += 8) {
        float4 av = *(const float4*)(Q + (size_t)(rowBlk + aRow) * 512 + k0 + aCol);
        Qs[aCol + 0][aRow] = av.x; Qs[aCol + 1][aRow] = av.y;
        Qs[aCol + 2][aRow] = av.z; Qs[aCol + 3][aRow] = av.w;
        float4 bv = *(const float4*)(K + (size_t)(colBlk + aRow) * 512 + k0 + aCol);
        Ks[aCol + 0][aRow] = bv.x; Ks[aCol + 1][aRow] = bv.y;
        Ks[aCol + 2][aRow] = bv.z; Ks[aCol + 3][aRow] = bv.w;
        __syncthreads();
#pragma unroll
        for (int kk = 0; kk < 8; kk++) {
            float a[8], bb[8];
            *(float4*)(a)      = *(const float4*)&Qs[kk][ty * 4];
            *(float4*)(a + 4)  = *(const float4*)&Qs[kk][64 + ty * 4];
            *(float4*)(bb)     = *(const float4*)&Ks[kk][tx * 4];
            *(float4*)(bb + 4) = *(const float4*)&Ks[kk][64 + tx * 4];
#pragma unroll
            for (int i = 0; i < 8; i++)
#pragma unroll
                for (int j = 0; j < 8; j++) acc[i][j] += a[i] * bb[j];
        }
        __syncthreads();
    }

    const float alpha = 0.125f * mw[qm[0] * H_NUM + h] * mw[km[0] * H_NUM + h];
    const float sy = tsync[t * H_NUM + h];
#pragma unroll
    for (int ih = 0; ih < 2; ih++)
#pragma unroll
        for (int i = 0; i < 4; i++) {
            const int r = rowBlk + ih * 64 + ty * 4 + i;
#pragma unroll
            for (int jh = 0; jh < 2; jh++) {
                const int c = colBlk + jh * 64 + tx * 4;
                float4 v;
                v.x = acc[ih * 4 + i][jh * 4 + 0] * alpha + sy;
                v.y = acc[ih * 4 + i][jh * 4 + 1] * alpha + sy;
                v.z = acc[ih * 4 + i][jh * 4 + 2] * alpha + sy;
                v.w = acc[ih * 4 + i][jh * 4 + 3] * alpha + sy;
                *(float4*)(S + (size_t)r * SEQ + c) = v;
            }
        }
}

// ============================================================================
// Kernel 3/5: spike softmax, one warp per score row of 512.
// p = sigmoid((s - max)*5); out = p / (sum(p) + 1e-8)
// grid = PBATCH*SEQ/8 = 16384, block = 256 (8 warps)
// ============================================================================
__global__ __launch_bounds__(256) void spike_softmax(float* __restrict__ scores)
{
    const size_t row = (size_t)blockIdx.x * 8 + (threadIdx.x >> 5);
    const int lane = threadIdx.x & 31;
    float* prow = scores + row * SEQ;

    float v[16];
    float m = -1e30f;
#pragma unroll
    for (int i = 0; i < 16; i++) {
        v[i] = prow[lane + i * 32];
        m = fmaxf(m, v[i]);
    }
#pragma unroll
    for (int o = 16; o > 0; o >>= 1) m = fmaxf(m, __shfl_xor_sync(0xFFFFFFFFu, m, o));

    float s = 0.f;
#pragma unroll
    for (int i = 0; i < 16; i++) {
        v[i] = 1.f / (1.f + __expf(-5.f * (v[i] - m)));
        s += v[i];
    }
#pragma unroll
    for (int o = 16; o > 0; o >>= 1) s += __shfl_xor_sync(0xFFFFFFFFu, s, o);

    const float inv = 1.f / (s + 1e-8f);
#pragma unroll
    for (int i = 0; i < 16; i++) prow[lane + i * 32] = v[i] * inv;
}

// ============================================================================
// Kernel 4/5: attended = attn @ V   per batch: [512x512] @ [512x64]
// BM=128, BN=64, BK=8, per-thread 8x4. grid = (4, 256), block = 256.
// Writes into g_att in [B,T,S,D] layout (col offset h*64, row stride 512).
// ============================================================================
__global__ __launch_bounds__(256) void attnv_gemm()
{
    const int p = blockIdx.y;
    const int h = p & 7;
    const int t = (p >> 3) & 15;
    const int b = p >> 7;
    const float* Aattn = g_scores + (size_t)p * SEQ * SEQ;
    const size_t vbase = ((size_t)(b * T_STEPS + t) * SEQ) * 512 + h * HD;
    const float* V = g_V + vbase;
    float* C = g_att + vbase;

    __shared__ float As[8][128];
    __shared__ float Vs[8][64];
    const int tid = threadIdx.x;
    const int tx = tid & 15, ty = tid >> 4;
    const int rowBlk = blockIdx.x * 128;
    const int aRow = tid >> 1, aCol = (tid & 1) * 4;
    const int vRow = tid >> 5, vCol = (tid & 31) * 2;

    float acc[8][4] = {};
    for (int k0 = 0; k0 < SEQ; k0 += 8) {
        float4 av = *(const float4*)(Aattn + (size_t)(rowBlk + aRow) * SEQ + k0 + aCol);
        As[aCol + 0][aRow] = av.x; As[aCol + 1][aRow] = av.y;
        As[aCol + 2][aRow] = av.z; As[aCol + 3][aRow] = av.w;
        *(float2*)&Vs[vRow][vCol] = *(const float2*)(V + (size_t)(k0 + vRow) * 512 + vCol);
        __syncthreads();
#pragma unroll
        for (int kk = 0; kk < 8; kk++) {
            float a[8], bb[4];
            *(float4*)(a)     = *(const float4*)&As[kk][ty * 4];
            *(float4*)(a + 4) = *(const float4*)&As[kk][64 + ty * 4];
            *(float4*)(bb)    = *(const float4*)&Vs[kk][tx * 4];
#pragma unroll
            for (int i = 0; i < 8; i++)
#pragma unroll
                for (int j = 0; j < 4; j++) acc[i][j] += a[i] * bb[j];
        }
        __syncthreads();
    }
#pragma unroll
    for (int ih = 0; ih < 2; ih++)
#pragma unroll
        for (int i = 0; i < 4; i++) {
            const int r = rowBlk + ih * 64 + ty * 4 + i;
            float4 v;
            v.x = acc[ih * 4 + i][0]; v.y = acc[ih * 4 + i][1];
            v.z = acc[ih * 4 + i][2]; v.w = acc[ih * 4 + i][3];
            *(float4*)(C + (size_t)r * 512 + tx * 4) = v;
        }
}

// ============================================================================
// launch
// ============================================================================
extern "C" void kernel_launch(void* const* d_in, const int* in_sizes, int n_in,
                              void* d_out, int out_size)
{
    const float* q_sp = (const float*)d_in[0];
    const float* k_sp = (const float*)d_in[1];
    const float* v_sp = (const float*)d_in[2];
    const float* Wq = (const float*)d_in[3];  const float* bq = (const float*)d_in[4];
    const float* Wk = (const float*)d_in[5];  const float* bk = (const float*)d_in[6];
    const float* Wv = (const float*)d_in[7];  const float* bv = (const float*)d_in[8];
    const float* Wo = (const float*)d_in[9];  const float* bo = (const float*)d_in[10];
    const float* mw    = (const float*)d_in[11];
    const float* tsync = (const float*)d_in[12];
    const int* qm = (const int*)d_in[13];
    const int* km = (const int*)d_in[14];
    float* out = (float*)d_out;

    float *dQ, *dK, *dV, *dAtt, *dS;
    cudaGetSymbolAddress((void**)&dQ, g_Q);
    cudaGetSymbolAddress((void**)&dK, g_K);
    cudaGetSymbolAddress((void**)&dV, g_V);
    cudaGetSymbolAddress((void**)&dAtt, g_att);
    cudaGetSymbolAddress((void**)&dS, g_scores);

    dim3 gProj(D_EMB / 128, M_ROWS / 128);   // (4, 128)
    proj_gemm<<<gProj, 256>>>(q_sp, Wq, bq, dQ);
    proj_gemm<<<gProj, 256>>>(k_sp, Wk, bk, dK);
    proj_gemm<<<gProj, 256>>>(v_sp, Wv, bv, dV);

    dim3 gScores(SEQ / 128, SEQ / 128, PBATCH);  // (4, 4, 256)
    scores_gemm<<<gScores, 256>>>(mw, tsync, qm, km);

    spike_softmax<<<(PBATCH * SEQ) / 8, 256>>>(dS);

    dim3 gAV(SEQ / 128, PBATCH);  // (4, 256)
    attnv_gemm<<<gAV, 256>>>();

    proj_gemm<<<gProj, 256>>>(dAtt, Wo, bo, out);
}

// round 2
// speedup vs baseline: 1.8064x; 1.8064x over previous
#include <cuda_runtime.h>
#include <stdint.h>

// Problem constants
#define D_EMB   512
#define H_NUM   8
#define T_STEPS 16
#define NB      2
#define SEQ     512
#define HD      64
#define M_ROWS  (NB * T_STEPS * SEQ)      // 16384
#define PBATCH  (NB * T_STEPS * H_NUM)    // 256

// ---- scratch (device globals; no runtime allocation allowed) ----
__device__ float g_Q[(size_t)M_ROWS * D_EMB];
__device__ float g_K[(size_t)M_ROWS * D_EMB];
__device__ float g_V[(size_t)M_ROWS * D_EMB];
__device__ float g_att[(size_t)M_ROWS * D_EMB];
__device__ float g_scores[(size_t)PBATCH * SEQ * SEQ];   // 256 MB

// ---- TF32 helpers ----
__device__ __forceinline__ uint32_t f2tf(float x) {
    uint32_t r;
    asm("cvt.rna.tf32.f32 %0, %1;" : "=r"(r) : "f"(x));
    return r;
}

// D += A(16x8) * B(8x8), tf32 inputs, f32 accum
__device__ __forceinline__ void mma8(float* c, const uint32_t* a, uint32_t b0, uint32_t b1) {
    asm volatile(
        "mma.sync.aligned.m16n8k8.row.col.f32.tf32.tf32.f32 "
        "{%0,%1,%2,%3}, {%4,%5,%6,%7}, {%8,%9}, {%0,%1,%2,%3};"
        : "+f"(c[0]), "+f"(c[1]), "+f"(c[2]), "+f"(c[3])
        : "r"(a[0]), "r"(a[1]), "r"(a[2]), "r"(a[3]), "r"(b0), "r"(b1));
}

// ============================================================================
// Kernel 1/5: projection GEMM  C[M,512] = A[M,512] @ W[512,512] + bias
// BM=128, BN=128, BK=32; 8 warps as 4(M)x2(N); warp tile 32x64.
// grid = (4, 128), block = 256
// ============================================================================
__global__ __launch_bounds__(256, 2) void proj_gemm(
    const float* __restrict__ A, const float* __restrict__ W,
    const float* __restrict__ bias, float* __restrict__ C)
{
    __shared__ uint32_t As[32][132];   // [k][m]
    __shared__ uint32_t Bs[32][132];   // [k][n]
    const int tid  = threadIdx.x;
    const int lane = tid & 31, warp = tid >> 5;
    const int g = lane >> 2, t = lane & 3;
    const int wm = (warp >> 1) * 32;
    const int wn = (warp & 1) * 64;
    const int rowBlk = blockIdx.y * 128;
    const int colBlk = blockIdx.x * 128;

    float acc[2][8][4] = {};
    for (int k0 = 0; k0 < 512; k0 += 32) {
#pragma unroll
        for (int i = 0; i < 4; i++) {               // A tile 128x32, scatter-transpose
            int idx = i * 256 + tid;
            int r = idx >> 3, c4 = (idx & 7) * 4;
            float4 v = *(const float4*)(A + (size_t)(rowBlk + r) * 512 + k0 + c4);
            As[c4 + 0][r] = f2tf(v.x); As[c4 + 1][r] = f2tf(v.y);
            As[c4 + 2][r] = f2tf(v.z); As[c4 + 3][r] = f2tf(v.w);
        }
#pragma unroll
        for (int i = 0; i < 4; i++) {               // W tile 32x128, direct
            int idx = i * 256 + tid;
            int kr = idx >> 5, c4 = (idx & 31) * 4;
            float4 v = *(const float4*)(W + (size_t)(k0 + kr) * 512 + colBlk + c4);
            Bs[kr][c4 + 0] = f2tf(v.x); Bs[kr][c4 + 1] = f2tf(v.y);
            Bs[kr][c4 + 2] = f2tf(v.z); Bs[kr][c4 + 3] = f2tf(v.w);
        }
        __syncthreads();
#pragma unroll
        for (int ks = 0; ks < 4; ks++) {
            const int kc = ks * 8 + t;
            uint32_t a[2][4];
#pragma unroll
            for (int mi = 0; mi < 2; mi++) {
                int m = wm + mi * 16 + g;
                a[mi][0] = As[kc][m];     a[mi][1] = As[kc][m + 8];
                a[mi][2] = As[kc + 4][m]; a[mi][3] = As[kc + 4][m + 8];
            }
#pragma unroll
            for (int ni = 0; ni < 8; ni++) {
                int n = wn + ni * 8 + g;
                uint32_t b0 = Bs[kc][n], b1 = Bs[kc + 4][n];
                mma8(acc[0][ni], a[0], b0, b1);
                mma8(acc[1][ni], a[1], b0, b1);
            }
        }
        __syncthreads();
    }
#pragma unroll
    for (int mi = 0; mi < 2; mi++) {
#pragma unroll
        for (int ni = 0; ni < 8; ni++) {
            const int col = colBlk + wn + ni * 8 + 2 * t;
            const float bx = bias[col], by = bias[col + 1];
            const int r0 = rowBlk + wm + mi * 16 + g;
            float2 v0 = {acc[mi][ni][0] + bx, acc[mi][ni][1] + by};
            *(float2*)(C + (size_t)r0 * 512 + col) = v0;
            float2 v1 = {acc[mi][ni][2] + bx, acc[mi][ni][3] + by};
            *(float2*)(C + (size_t)(r0 + 8) * 512 + col) = v1;
        }
    }
}

// ============================================================================
// Kernel 2/5: batched scores  S[p,q,k] = (Q.K/8)*modw + sync
// Per p=(b,t,h): Q,K are 512x64 with row stride 512. NT GEMM, Kdim=64.
// grid = (4, 4, 256), block = 256
// ============================================================================
__global__ __launch_bounds__(256, 2) void scores_gemm(
    const float* __restrict__ mw, const float* __restrict__ tsync,
    const int* __restrict__ qm, const int* __restrict__ km)
{
    const int p = blockIdx.z;
    const int h = p & 7;
    const int tt = (p >> 3) & 15;
    const int b = p >> 7;
    const size_t base = ((size_t)(b * T_STEPS + tt) * SEQ) * 512 + h * HD;
    const float* Q = g_Q + base;
    const float* K = g_K + base;
    float* S = g_scores + (size_t)p * SEQ * SEQ;

    __shared__ uint32_t As[32][132];   // [k][q]
    __shared__ uint32_t Bs[32][132];   // [k][kk]
    const int tid  = threadIdx.x;
    const int lane = tid & 31, warp = tid >> 5;
    const int g = lane >> 2, t = lane & 3;
    const int wm = (warp >> 1) * 32;
    const int wn = (warp & 1) * 64;
    const int rowBlk = blockIdx.y * 128;
    const int colBlk = blockIdx.x * 128;

    float acc[2][8][4] = {};
    for (int k0 = 0; k0 < HD; k0 += 32) {
#pragma unroll
        for (int i = 0; i < 4; i++) {
            int idx = i * 256 + tid;
            int r = idx >> 3, c4 = (idx & 7) * 4;
            float4 v = *(const float4*)(Q + (size_t)(rowBlk + r) * 512 + k0 + c4);
            As[c4 + 0][r] = f2tf(v.x); As[c4 + 1][r] = f2tf(v.y);
            As[c4 + 2][r] = f2tf(v.z); As[c4 + 3][r] = f2tf(v.w);
        }
#pragma unroll
        for (int i = 0; i < 4; i++) {
            int idx = i * 256 + tid;
            int r = idx >> 3, c4 = (idx & 7) * 4;
            float4 v = *(const float4*)(K + (size_t)(colBlk + r) * 512 + k0 + c4);
            Bs[c4 + 0][r] = f2tf(v.x); Bs[c4 + 1][r] = f2tf(v.y);
            Bs[c4 + 2][r] = f2tf(v.z); Bs[c4 + 3][r] = f2tf(v.w);
        }
        __syncthreads();
#pragma unroll
        for (int ks = 0; ks < 4; ks++) {
            const int kc = ks * 8 + t;
            uint32_t a[2][4];
#pragma unroll
            for (int mi = 0; mi < 2; mi++) {
                int m = wm + mi * 16 + g;
                a[mi][0] = As[kc][m];     a[mi][1] = As[kc][m + 8];
                a[mi][2] = As[kc + 4][m]; a[mi][3] = As[kc + 4][m + 8];
            }
#pragma unroll
            for (int ni = 0; ni < 8; ni++) {
                int n = wn + ni * 8 + g;
                uint32_t b0 = Bs[kc][n], b1 = Bs[kc + 4][n];
                mma8(acc[0][ni], a[0], b0, b1);
                mma8(acc[1][ni], a[1], b0, b1);
            }
        }
        __syncthreads();
    }

    const float alpha = 0.125f * mw[qm[0] * H_NUM + h] * mw[km[0] * H_NUM + h];
    const float sy = tsync[tt * H_NUM + h];
#pragma unroll
    for (int mi = 0; mi < 2; mi++) {
#pragma unroll
        for (int ni = 0; ni < 8; ni++) {
            const int col = colBlk + wn + ni * 8 + 2 * t;
            const int r0 = rowBlk + wm + mi * 16 + g;
            float2 v0 = {acc[mi][ni][0] * alpha + sy, acc[mi][ni][1] * alpha + sy};
            *(float2*)(S + (size_t)r0 * SEQ + col) = v0;
            float2 v1 = {acc[mi][ni][2] * alpha + sy, acc[mi][ni][3] * alpha + sy};
            *(float2*)(S + (size_t)(r0 + 8) * SEQ + col) = v1;
        }
    }
}

// ============================================================================
// Kernel 3/5: spike softmax, one warp per row of 512.
// ============================================================================
__global__ __launch_bounds__(256) void spike_softmax(float* __restrict__ scores)
{
    const size_t row = (size_t)blockIdx.x * 8 + (threadIdx.x >> 5);
    const int lane = threadIdx.x & 31;
    float* prow = scores + row * SEQ;

    float v[16];
    float m = -1e30f;
#pragma unroll
    for (int i = 0; i < 16; i++) {
        v[i] = prow[lane + i * 32];
        m = fmaxf(m, v[i]);
    }
#pragma unroll
    for (int o = 16; o > 0; o >>= 1) m = fmaxf(m, __shfl_xor_sync(0xFFFFFFFFu, m, o));

    float s = 0.f;
#pragma unroll
    for (int i = 0; i < 16; i++) {
        v[i] = 1.f / (1.f + __expf(-5.f * (v[i] - m)));
        s += v[i];
    }
#pragma unroll
    for (int o = 16; o > 0; o >>= 1) s += __shfl_xor_sync(0xFFFFFFFFu, s, o);

    const float inv = 1.f / (s + 1e-8f);
#pragma unroll
    for (int i = 0; i < 16; i++) prow[lane + i * 32] = v[i] * inv;
}

// ============================================================================
// Kernel 4/5: attended = attn @ V   per p: [512x512] @ [512x64]
// BM=128, BN=64, BK=32; 8 warps as 4x2; warp tile 32x32.
// grid = (4, 256), block = 256
// ============================================================================
__global__ __launch_bounds__(256, 2) void attnv_gemm()
{
    const int p = blockIdx.y;
    const int h = p & 7;
    const int tt = (p >> 3) & 15;
    const int b = p >> 7;
    const float* Aattn = g_scores + (size_t)p * SEQ * SEQ;
    const size_t vbase = ((size_t)(b * T_STEPS + tt) * SEQ) * 512 + h * HD;
    const float* V = g_V + vbase;
    float* C = g_att + vbase;

    __shared__ uint32_t As[32][132];   // [k][m]
    __shared__ uint32_t Bs[32][68];    // [k][n]
    const int tid  = threadIdx.x;
    const int lane = tid & 31, warp = tid >> 5;
    const int g = lane >> 2, t = lane & 3;
    const int wm = (warp >> 1) * 32;
    const int wn = (warp & 1) * 32;
    const int rowBlk = blockIdx.x * 128;

    float acc[2][4][4] = {};
    for (int k0 = 0; k0 < SEQ; k0 += 32) {
#pragma unroll
        for (int i = 0; i < 4; i++) {               // attn tile 128x32, scatter-transpose
            int idx = i * 256 + tid;
            int r = idx >> 3, c4 = (idx & 7) * 4;
            float4 v = *(const float4*)(Aattn + (size_t)(rowBlk + r) * SEQ + k0 + c4);
            As[c4 + 0][r] = f2tf(v.x); As[c4 + 1][r] = f2tf(v.y);
            As[c4 + 2][r] = f2tf(v.z); As[c4 + 3][r] = f2tf(v.w);
        }
#pragma unroll
        for (int i = 0; i < 2; i++) {               // V tile 32x64, direct
            int idx = i * 256 + tid;
            int kr = idx >> 4, c4 = (idx & 15) * 4;
            float4 v = *(const float4*)(V + (size_t)(k0 + kr) * 512 + c4);
            Bs[kr][c4 + 0] = f2tf(v.x); Bs[kr][c4 + 1] = f2tf(v.y);
            Bs[kr][c4 + 2] = f2tf(v.z); Bs[kr][c4 + 3] = f2tf(v.w);
        }
        __syncthreads();
#pragma unroll
        for (int ks = 0; ks < 4; ks++) {
            const int kc = ks * 8 + t;
            uint32_t a[2][4];
#pragma unroll
            for (int mi = 0; mi < 2; mi++) {
                int m = wm + mi * 16 + g;
                a[mi][0] = As[kc][m];     a[mi][1] = As[kc][m + 8];
                a[mi][2] = As[kc + 4][m]; a[mi][3] = As[kc + 4][m + 8];
            }
#pragma unroll
            for (int ni = 0; ni < 4; ni++) {
                int n = wn + ni * 8 + g;
                uint32_t b0 = Bs[kc][n], b1 = Bs[kc + 4][n];
                mma8(acc[0][ni], a[0], b0, b1);
                mma8(acc[1][ni], a[1], b0, b1);
            }
        }
        __syncthreads();
    }
#pragma unroll
    for (int mi = 0; mi < 2; mi++) {
#pragma unroll
        for (int ni = 0; ni < 4; ni++) {
            const int col = wn + ni * 8 + 2 * t;
            const int r0 = rowBlk + wm + mi * 16 + g;
            float2 v0 = {acc[mi][ni][0], acc[mi][ni][1]};
            *(float2*)(C + (size_t)r0 * 512 + col) = v0;
            float2 v1 = {acc[mi][ni][2], acc[mi][ni][3]};
            *(float2*)(C + (size_t)(r0 + 8) * 512 + col) = v1;
        }
    }
}

// ============================================================================
// launch
// ============================================================================
extern "C" void kernel_launch(void* const* d_in, const int* in_sizes, int n_in,
                              void* d_out, int out_size)
{
    const float* q_sp = (const float*)d_in[0];
    const float* k_sp = (const float*)d_in[1];
    const float* v_sp = (const float*)d_in[2];
    const float* Wq = (const float*)d_in[3];  const float* bq = (const float*)d_in[4];
    const float* Wk = (const float*)d_in[5];  const float* bk = (const float*)d_in[6];
    const float* Wv = (const float*)d_in[7];  const float* bv = (const float*)d_in[8];
    const float* Wo = (const float*)d_in[9];  const float* bo = (const float*)d_in[10];
    const float* mw    = (const float*)d_in[11];
    const float* tsync = (const float*)d_in[12];
    const int* qm = (const int*)d_in[13];
    const int* km = (const int*)d_in[14];
    float* out = (float*)d_out;

    float *dQ, *dK, *dV, *dAtt, *dS;
    cudaGetSymbolAddress((void**)&dQ, g_Q);
    cudaGetSymbolAddress((void**)&dK, g_K);
    cudaGetSymbolAddress((void**)&dV, g_V);
    cudaGetSymbolAddress((void**)&dAtt, g_att);
    cudaGetSymbolAddress((void**)&dS, g_scores);

    dim3 gProj(D_EMB / 128, M_ROWS / 128);   // (4, 128)
    proj_gemm<<<gProj, 256>>>(q_sp, Wq, bq, dQ);
    proj_gemm<<<gProj, 256>>>(k_sp, Wk, bk, dK);
    proj_gemm<<<gProj, 256>>>(v_sp, Wv, bv, dV);

    dim3 gScores(SEQ / 128, SEQ / 128, PBATCH);  // (4, 4, 256)
    scores_gemm<<<gScores, 256>>>(mw, tsync, qm, km);

    spike_softmax<<<(PBATCH * SEQ) / 8, 256>>>(dS);

    dim3 gAV(SEQ / 128, PBATCH);  // (4, 256)
    attnv_gemm<<<gAV, 256>>>();

    proj_gemm<<<gProj, 256>>>(dAtt, Wo, bo, out);
}

// round 4
// speedup vs baseline: 2.1077x; 1.1668x over previous
#include <cuda_runtime.h>
#include <stdint.h>

#define D_EMB   512
#define H_NUM   8
#define T_STEPS 16
#define NB      2
#define SEQ     512
#define HD      64
#define M_ROWS  (NB * T_STEPS * SEQ)      // 16384
#define PBATCH  (NB * T_STEPS * H_NUM)    // 256

// ---- scratch ----
__device__ float g_Q[(size_t)M_ROWS * D_EMB];
__device__ float g_K[(size_t)M_ROWS * D_EMB];
__device__ float g_V[(size_t)M_ROWS * D_EMB];
__device__ float g_att[(size_t)M_ROWS * D_EMB];

// ---- helpers ----
__device__ __forceinline__ uint32_t f2tf(float x) {
    uint32_t r;
    asm("cvt.rna.tf32.f32 %0, %1;" : "=r"(r) : "f"(x));
    return r;
}
__device__ __forceinline__ void mma8(float* c, const uint32_t* a, uint32_t b0, uint32_t b1) {
    asm volatile(
        "mma.sync.aligned.m16n8k8.row.col.f32.tf32.tf32.f32 "
        "{%0,%1,%2,%3}, {%4,%5,%6,%7}, {%8,%9}, {%0,%1,%2,%3};"
        : "+f"(c[0]), "+f"(c[1]), "+f"(c[2]), "+f"(c[3])
        : "r"(a[0]), "r"(a[1]), "r"(a[2]), "r"(a[3]), "r"(b0), "r"(b1));
}
__device__ __forceinline__ void cpa16(uint32_t dst, const void* src) {
    asm volatile("cp.async.ca.shared.global [%0], [%1], 16;" :: "r"(dst), "l"(src));
}
__device__ __forceinline__ void cpa_commit() { asm volatile("cp.async.commit_group;"); }
__device__ __forceinline__ void cpa_wait1() { asm volatile("cp.async.wait_group 1;"); }
__device__ __forceinline__ void cpa_wait0() { asm volatile("cp.async.wait_group 0;"); }

// ============================================================================
// projection GEMM: C[M,512] = A[M,512] @ W[512,512] + bias
// cp.async double-buffered, BK=32. A tile [128][36] as-is, W tile [32][136].
// 8 warps 4(M)x2(N), warp tile 32x64. grid=(4, M/128), block=256.
// dyn smem = 71680 B
// ============================================================================
#define PJ_AS_W 4608   // 128*36 words per buffer
#define PJ_WS_W 4352   // 32*136 words per buffer
__global__ __launch_bounds__(256, 2) void proj_gemm(
    const float* __restrict__ A, const float* __restrict__ W,
    const float* __restrict__ bias, float* __restrict__ C)
{
    extern __shared__ __align__(16) unsigned char smraw[];
    float* As = (float*)smraw;                       // [2][128][36]
    float* Ws = (float*)(smraw + 2 * PJ_AS_W * 4);   // [2][32][136]
    const uint32_t sAs = (uint32_t)__cvta_generic_to_shared(As);
    const uint32_t sWs = (uint32_t)__cvta_generic_to_shared(Ws);

    const int tid = threadIdx.x;
    const int lane = tid & 31, warp = tid >> 5;
    const int g = lane >> 2, t = lane & 3;
    const int wm = (warp >> 1) * 32;
    const int wn = (warp & 1) * 64;
    const int rowBlk = blockIdx.y * 128;
    const int colBlk = blockIdx.x * 128;

    auto issue = [&](int st) {
        const int buf = st & 1;
        const int k0 = st * 32;
#pragma unroll
        for (int i = 0; i < 4; i++) {
            int seg = i * 256 + tid;
            int r = seg >> 3, s = (seg & 7) << 2;
            cpa16(sAs + ((buf * PJ_AS_W + r * 36 + s) << 2),
                  A + (size_t)(rowBlk + r) * 512 + k0 + s);
        }
#pragma unroll
        for (int i = 0; i < 4; i++) {
            int seg = i * 256 + tid;
            int kr = seg >> 5, s = (seg & 31) << 2;
            cpa16(sWs + ((buf * PJ_WS_W + kr * 136 + s) << 2),
                  W + (size_t)(k0 + kr) * 512 + colBlk + s);
        }
        cpa_commit();
    };

    float acc[2][8][4] = {};
    issue(0);
    for (int st = 0; st < 16; st++) {
        if (st + 1 < 16) { issue(st + 1); cpa_wait1(); } else cpa_wait0();
        __syncthreads();
        const float* Ab = As + (st & 1) * PJ_AS_W;
        const float* Wb = Ws + (st & 1) * PJ_WS_W;
#pragma unroll
        for (int ks = 0; ks < 4; ks++) {
            const int kc = ks * 8 + t;
            uint32_t a[2][4];
#pragma unroll
            for (int mi = 0; mi < 2; mi++) {
                const int m = wm + mi * 16 + g;
                a[mi][0] = f2tf(Ab[m * 36 + kc]);
                a[mi][1] = f2tf(Ab[(m + 8) * 36 + kc]);
                a[mi][2] = f2tf(Ab[m * 36 + kc + 4]);
                a[mi][3] = f2tf(Ab[(m + 8) * 36 + kc + 4]);
            }
#pragma unroll
            for (int ni = 0; ni < 8; ni++) {
                const int n = wn + ni * 8 + g;
                uint32_t b0 = f2tf(Wb[kc * 136 + n]);
                uint32_t b1 = f2tf(Wb[(kc + 4) * 136 + n]);
                mma8(acc[0][ni], a[0], b0, b1);
                mma8(acc[1][ni], a[1], b0, b1);
            }
        }
        __syncthreads();
    }
#pragma unroll
    for (int mi = 0; mi < 2; mi++)
#pragma unroll
        for (int ni = 0; ni < 8; ni++) {
            const int col = colBlk + wn + ni * 8 + 2 * t;
            const float bx = bias[col], by = bias[col + 1];
            const int r0 = rowBlk + wm + mi * 16 + g;
            float2 v0 = {acc[mi][ni][0] + bx, acc[mi][ni][1] + by};
            *(float2*)(C + (size_t)r0 * 512 + col) = v0;
            float2 v1 = {acc[mi][ni][2] + bx, acc[mi][ni][3] + by};
            *(float2*)(C + (size_t)(r0 + 8) * 512 + col) = v1;
        }
}

// ============================================================================
// fused attention: per (p, qtile): scores -> spike softmax -> attn@V
// S tile [512 keys][72] fp32/tf32 in smem; Q [64][68]; K dbuf [2][64][68];
// V dbuf [2][64][72] (union with Q/K). dyn smem = 199680 B.
// grid = (8 qtiles, 256 p), block = 256 (8 warps).
// ============================================================================
#define FS_S_W   72
#define FS_QK_W  68
#define FS_KBUF  (64 * FS_QK_W)    // words per K buffer
#define FS_VBUF  (64 * FS_S_W)     // words per V buffer
#define FS_UOFF  147456            // byte offset of union region (512*72*4)
__global__ __launch_bounds__(256, 1) void fused_attn(
    const float* __restrict__ mw, const float* __restrict__ tsync,
    const int* __restrict__ qm, const int* __restrict__ km)
{
    extern __shared__ __align__(16) unsigned char smraw[];
    float*    Sf = (float*)smraw;                       // [512][72]
    uint32_t* Su = (uint32_t*)smraw;
    float*    Qs = (float*)(smraw + FS_UOFF);           // [64][68]
    float*    Ks = (float*)(smraw + FS_UOFF + 64 * FS_QK_W * 4);  // [2][64][68]
    float*    Vs = (float*)(smraw + FS_UOFF);           // [2][64][72] (union)
    const uint32_t sQ = (uint32_t)__cvta_generic_to_shared(Qs);
    const uint32_t sK = (uint32_t)__cvta_generic_to_shared(Ks);
    const uint32_t sV = (uint32_t)__cvta_generic_to_shared(Vs);

    const int tid = threadIdx.x;
    const int lane = tid & 31, warp = tid >> 5;
    const int g = lane >> 2, t = lane & 3;

    const int tile = blockIdx.x;
    const int p = blockIdx.y;
    const int h = p & 7;
    const int tt = (p >> 3) & 15;
    const int b = p >> 7;
    const size_t rowbase = ((size_t)(b * T_STEPS + tt) * SEQ);
    const float* Qg = g_Q + (rowbase + tile * 64) * 512 + h * HD;
    const float* Kg = g_K + rowbase * 512 + h * HD;
    const float* Vg = g_V + rowbase * 512 + h * HD;
    float*       Cg = g_att + (rowbase + tile * 64) * 512 + h * HD;

    const float alpha = 0.125f * mw[qm[0] * H_NUM + h] * mw[km[0] * H_NUM + h];
    const float sy = tsync[tt * H_NUM + h];

    // ---------------- phase 1: scores into S ----------------
    const int wm = (warp >> 2) * 32;     // 2 warp-rows of M=64
    const int wn = (warp & 3) * 16;      // 4 warp-cols of N=64 chunk

    // prologue: Q + K chunk 0 in one group
    {
#pragma unroll
        for (int i = 0; i < 4; i++) {
            int seg = i * 256 + tid;
            int r = seg >> 4, s = (seg & 15) << 2;
            cpa16(sQ + ((r * FS_QK_W + s) << 2), Qg + (size_t)r * 512 + s);
        }
#pragma unroll
        for (int i = 0; i < 4; i++) {
            int seg = i * 256 + tid;
            int r = seg >> 4, s = (seg & 15) << 2;
            cpa16(sK + ((r * FS_QK_W + s) << 2), Kg + (size_t)r * 512 + s);
        }
        cpa_commit();
    }

    for (int c = 0; c < 8; c++) {
        if (c + 1 < 8) {   // issue next K chunk
            const int buf = (c + 1) & 1;
#pragma unroll
            for (int i = 0; i < 4; i++) {
                int seg = i * 256 + tid;
                int r = seg >> 4, s = (seg & 15) << 2;
                cpa16(sK + ((buf * FS_KBUF + r * FS_QK_W + s) << 2),
                      Kg + (size_t)((c + 1) * 64 + r) * 512 + s);
            }
            cpa_commit();
            cpa_wait1();
        } else cpa_wait0();
        __syncthreads();

        const float* Kb = Ks + (c & 1) * FS_KBUF;
        float acc[2][2][4] = {};
#pragma unroll
        for (int ks = 0; ks < 8; ks++) {
            const int kc = ks * 8 + t;
            uint32_t a[2][4];
#pragma unroll
            for (int mi = 0; mi < 2; mi++) {
                const int m = wm + mi * 16 + g;
                a[mi][0] = f2tf(Qs[m * FS_QK_W + kc]);
                a[mi][1] = f2tf(Qs[(m + 8) * FS_QK_W + kc]);
                a[mi][2] = f2tf(Qs[m * FS_QK_W + kc + 4]);
                a[mi][3] = f2tf(Qs[(m + 8) * FS_QK_W + kc + 4]);
            }
#pragma unroll
            for (int ni = 0; ni < 2; ni++) {
                const int n = wn + ni * 8 + g;
                uint32_t b0 = f2tf(Kb[n * FS_QK_W + kc]);
                uint32_t b1 = f2tf(Kb[n * FS_QK_W + kc + 4]);
                mma8(acc[0][ni], a[0], b0, b1);
                mma8(acc[1][ni], a[1], b0, b1);
            }
        }
        // store fragment -> S (transposed: S[key][qrow]), with scale+bias
#pragma unroll
        for (int mi = 0; mi < 2; mi++)
#pragma unroll
            for (int ni = 0; ni < 2; ni++) {
                const int n0 = c * 64 + wn + ni * 8 + 2 * t;
                const int r0 = wm + mi * 16 + g;
                Sf[n0 * FS_S_W + r0]           = acc[mi][ni][0] * alpha + sy;
                Sf[(n0 + 1) * FS_S_W + r0]     = acc[mi][ni][1] * alpha + sy;
                Sf[n0 * FS_S_W + r0 + 8]       = acc[mi][ni][2] * alpha + sy;
                Sf[(n0 + 1) * FS_S_W + r0 + 8] = acc[mi][ni][3] * alpha + sy;
            }
        __syncthreads();
    }

    // prefetch V chunks 0,1 into union region (phase-1 reads are done)
    {
#pragma unroll
        for (int cc = 0; cc < 2; cc++) {
#pragma unroll
            for (int i = 0; i < 4; i++) {
                int seg = i * 256 + tid;
                int r = seg >> 4, s = (seg & 15) << 2;
                cpa16(sV + ((cc * FS_VBUF + r * FS_S_W + s) << 2),
                      Vg + (size_t)(cc * 64 + r) * 512 + s);
            }
            cpa_commit();
        }
    }

    // ---------------- softmax (row m of scores lives at S[:, m]) ----------
    {
        const int mrow = warp * 8 + (lane >> 2);   // 8 warps x 8 rows = 64
        const int np = lane & 3;
        float mx = -1e30f;
#pragma unroll 8
        for (int ci = 0; ci < 128; ci++)
            mx = fmaxf(mx, Sf[(np + 4 * ci) * FS_S_W + mrow]);
        mx = fmaxf(mx, __shfl_xor_sync(0xFFFFFFFFu, mx, 1));
        mx = fmaxf(mx, __shfl_xor_sync(0xFFFFFFFFu, mx, 2));
        float sum = 0.f;
#pragma unroll 8
        for (int ci = 0; ci < 128; ci++) {
            const int idx = (np + 4 * ci) * FS_S_W + mrow;
            float pv = 1.f / (1.f + __expf(-5.f * (Sf[idx] - mx)));
            Sf[idx] = pv;
            sum += pv;
        }
        sum += __shfl_xor_sync(0xFFFFFFFFu, sum, 1);
        sum += __shfl_xor_sync(0xFFFFFFFFu, sum, 2);
        const float inv = 1.f / (sum + 1e-8f);
#pragma unroll 8
        for (int ci = 0; ci < 128; ci++) {
            const int idx = (np + 4 * ci) * FS_S_W + mrow;
            Su[idx] = f2tf(Sf[idx] * inv);
        }
    }
    __syncthreads();

    // ---------------- phase 2: O = attn @ V ----------------
    const int wm2 = (warp >> 2) * 32;
    const int wn2 = (warp & 3) * 16;
    float acc2[2][2][4] = {};
    for (int c = 0; c < 8; c++) {
        if (c < 7) cpa_wait1(); else cpa_wait0();
        __syncthreads();
        const float* Vb = Vs + (c & 1) * FS_VBUF;
#pragma unroll
        for (int ks = 0; ks < 8; ks++) {
            const int kl = ks * 8 + t;
            const int kg = c * 64 + kl;
            uint32_t a[2][4];
#pragma unroll
            for (int mi = 0; mi < 2; mi++) {
                const int m = wm2 + mi * 16 + g;
                a[mi][0] = Su[kg * FS_S_W + m];
                a[mi][1] = Su[kg * FS_S_W + m + 8];
                a[mi][2] = Su[(kg + 4) * FS_S_W + m];
                a[mi][3] = Su[(kg + 4) * FS_S_W + m + 8];
            }
#pragma unroll
            for (int ni = 0; ni < 2; ni++) {
                const int n = wn2 + ni * 8 + g;
                uint32_t b0 = f2tf(Vb[kl * FS_S_W + n]);
                uint32_t b1 = f2tf(Vb[(kl + 4) * FS_S_W + n]);
                mma8(acc2[0][ni], a[0], b0, b1);
                mma8(acc2[1][ni], a[1], b0, b1);
            }
        }
        __syncthreads();
        if (c + 2 < 8) {   // refill freed buffer
            const int buf = c & 1;
#pragma unroll
            for (int i = 0; i < 4; i++) {
                int seg = i * 256 + tid;
                int r = seg >> 4, s = (seg & 15) << 2;
                cpa16(sV + ((buf * FS_VBUF + r * FS_S_W + s) << 2),
                      Vg + (size_t)((c + 2) * 64 + r) * 512 + s);
            }
            cpa_commit();
        }
    }
#pragma unroll
    for (int mi = 0; mi < 2; mi++)
#pragma unroll
        for (int ni = 0; ni < 2; ni++) {
            const int col = wn2 + ni * 8 + 2 * t;
            const int r0 = wm2 + mi * 16 + g;
            float2 v0 = {acc2[mi][ni][0], acc2[mi][ni][1]};
            *(float2*)(Cg + (size_t)r0 * 512 + col) = v0;
            float2 v1 = {acc2[mi][ni][2], acc2[mi][ni][3]};
            *(float2*)(Cg + (size_t)(r0 + 8) * 512 + col) = v1;
        }
}

// ============================================================================
// launch
// ============================================================================
#define PJ_SMEM 71680
#define FS_SMEM 199680
extern "C" void kernel_launch(void* const* d_in, const int* in_sizes, int n_in,
                              void* d_out, int out_size)
{
    const float* q_sp = (const float*)d_in[0];
    const float* k_sp = (const float*)d_in[1];
    const float* v_sp = (const float*)d_in[2];
    const float* Wq = (const float*)d_in[3];  const float* bq = (const float*)d_in[4];
    const float* Wk = (const float*)d_in[5];  const float* bk = (const float*)d_in[6];
    const float* Wv = (const float*)d_in[7];  const float* bv = (const float*)d_in[8];
    const float* Wo = (const float*)d_in[9];  const float* bo = (const float*)d_in[10];
    const float* mw    = (const float*)d_in[11];
    const float* tsync = (const float*)d_in[12];
    const int* qm = (const int*)d_in[13];
    const int* km = (const int*)d_in[14];
    float* out = (float*)d_out;

    // unconditional (no static guards): idempotent, not stream-ordered
    cudaFuncSetAttribute(proj_gemm, cudaFuncAttributeMaxDynamicSharedMemorySize, PJ_SMEM);
    cudaFuncSetAttribute(fused_attn, cudaFuncAttributeMaxDynamicSharedMemorySize, FS_SMEM);

    float *dQ, *dK, *dV, *dAtt;
    cudaGetSymbolAddress((void**)&dQ, g_Q);
    cudaGetSymbolAddress((void**)&dK, g_K);
    cudaGetSymbolAddress((void**)&dV, g_V);
    cudaGetSymbolAddress((void**)&dAtt, g_att);

    dim3 gProj(D_EMB / 128, M_ROWS / 128);   // (4, 128)
    proj_gemm<<<gProj, 256, PJ_SMEM>>>(q_sp, Wq, bq, dQ);
    proj_gemm<<<gProj, 256, PJ_SMEM>>>(k_sp, Wk, bk, dK);
    proj_gemm<<<gProj, 256, PJ_SMEM>>>(v_sp, Wv, bv, dV);

    fused_attn<<<dim3(SEQ / 64, PBATCH), 256, FS_SMEM>>>(mw, tsync, qm, km);

    proj_gemm<<<gProj, 256, PJ_SMEM>>>(dAtt, Wo, bo, out);
}

// round 6
// speedup vs baseline: 2.2865x; 1.0848x over previous
#include <cuda_runtime.h>
#include <stdint.h>

#define D_EMB   512
#define H_NUM   8
#define T_STEPS 16
#define NB      2
#define SEQ     512
#define HD      64
#define M_ROWS  (NB * T_STEPS * SEQ)      // 16384
#define PBATCH  (NB * T_STEPS * H_NUM)    // 256

// ---- scratch ----
__device__ float g_Q[(size_t)M_ROWS * D_EMB];
__device__ float g_K[(size_t)M_ROWS * D_EMB];
__device__ float g_V[(size_t)M_ROWS * D_EMB];
__device__ float g_att[(size_t)M_ROWS * D_EMB];

// ---- helpers ----
__device__ __forceinline__ uint32_t f2tf(float x) {
    uint32_t r;
    asm("cvt.rna.tf32.f32 %0, %1;" : "=r"(r) : "f"(x));
    return r;
}
__device__ __forceinline__ void mma8(float* c, const uint32_t* a, uint32_t b0, uint32_t b1) {
    asm volatile(
        "mma.sync.aligned.m16n8k8.row.col.f32.tf32.tf32.f32 "
        "{%0,%1,%2,%3}, {%4,%5,%6,%7}, {%8,%9}, {%0,%1,%2,%3};"
        : "+f"(c[0]), "+f"(c[1]), "+f"(c[2]), "+f"(c[3])
        : "r"(a[0]), "r"(a[1]), "r"(a[2]), "r"(a[3]), "r"(b0), "r"(b1));
}
__device__ __forceinline__ void cpa16(uint32_t dst, const void* src) {
    asm volatile("cp.async.ca.shared.global [%0], [%1], 16;" :: "r"(dst), "l"(src));
}
__device__ __forceinline__ void cpa_commit() { asm volatile("cp.async.commit_group;"); }
__device__ __forceinline__ void cpa_wait1() { asm volatile("cp.async.wait_group 1;"); }
__device__ __forceinline__ void cpa_wait0() { asm volatile("cp.async.wait_group 0;"); }

// ============================================================================
// merged projection GEMM: z selects (A,W,bias,C) triple.
// C[M,512] = A[M,512] @ W[512,512] + bias
// cp.async double-buffered, BK=32. A tile [128][36], W tile [32][136].
// 8 warps 4(M)x2(N), warp tile 32x64. grid=(4, M/128, nz), block=256.
// dyn smem = 71680 B
// ============================================================================
#define PJ_AS_W 4608   // 128*36 words per buffer
#define PJ_WS_W 4352   // 32*136 words per buffer
__global__ __launch_bounds__(256, 2) void proj3_gemm(
    const float* __restrict__ A0, const float* __restrict__ W0,
    const float* __restrict__ B0, float* __restrict__ C0,
    const float* __restrict__ A1, const float* __restrict__ W1,
    const float* __restrict__ B1, float* __restrict__ C1,
    const float* __restrict__ A2, const float* __restrict__ W2,
    const float* __restrict__ B2, float* __restrict__ C2)
{
    const int z = blockIdx.z;
    const float* A    = (z == 0) ? A0 : (z == 1) ? A1 : A2;
    const float* W    = (z == 0) ? W0 : (z == 1) ? W1 : W2;
    const float* bias = (z == 0) ? B0 : (z == 1) ? B1 : B2;
    float*       C    = (z == 0) ? C0 : (z == 1) ? C1 : C2;

    extern __shared__ __align__(16) unsigned char smraw[];
    float* As = (float*)smraw;                       // [2][128][36]
    float* Ws = (float*)(smraw + 2 * PJ_AS_W * 4);   // [2][32][136]
    const uint32_t sAs = (uint32_t)__cvta_generic_to_shared(As);
    const uint32_t sWs = (uint32_t)__cvta_generic_to_shared(Ws);

    const int tid = threadIdx.x;
    const int lane = tid & 31, warp = tid >> 5;
    const int g = lane >> 2, t = lane & 3;
    const int wm = (warp >> 1) * 32;
    const int wn = (warp & 1) * 64;
    const int rowBlk = blockIdx.y * 128;
    const int colBlk = blockIdx.x * 128;

    auto issue = [&](int st) {
        const int buf = st & 1;
        const int k0 = st * 32;
#pragma unroll
        for (int i = 0; i < 4; i++) {
            int seg = i * 256 + tid;
            int r = seg >> 3, s = (seg & 7) << 2;
            cpa16(sAs + ((buf * PJ_AS_W + r * 36 + s) << 2),
                  A + (size_t)(rowBlk + r) * 512 + k0 + s);
        }
#pragma unroll
        for (int i = 0; i < 4; i++) {
            int seg = i * 256 + tid;
            int kr = seg >> 5, s = (seg & 31) << 2;
            cpa16(sWs + ((buf * PJ_WS_W + kr * 136 + s) << 2),
                  W + (size_t)(k0 + kr) * 512 + colBlk + s);
        }
        cpa_commit();
    };

    float acc[2][8][4] = {};
    issue(0);
    for (int st = 0; st < 16; st++) {
        if (st + 1 < 16) { issue(st + 1); cpa_wait1(); } else cpa_wait0();
        __syncthreads();
        const float* Ab = As + (st & 1) * PJ_AS_W;
        const float* Wb = Ws + (st & 1) * PJ_WS_W;
#pragma unroll
        for (int ks = 0; ks < 4; ks++) {
            const int kc = ks * 8 + t;
            uint32_t a[2][4];
#pragma unroll
            for (int mi = 0; mi < 2; mi++) {
                const int m = wm + mi * 16 + g;
                a[mi][0] = f2tf(Ab[m * 36 + kc]);
                a[mi][1] = f2tf(Ab[(m + 8) * 36 + kc]);
                a[mi][2] = f2tf(Ab[m * 36 + kc + 4]);
                a[mi][3] = f2tf(Ab[(m + 8) * 36 + kc + 4]);
            }
#pragma unroll
            for (int ni = 0; ni < 8; ni++) {
                const int n = wn + ni * 8 + g;
                uint32_t b0 = f2tf(Wb[kc * 136 + n]);
                uint32_t b1 = f2tf(Wb[(kc + 4) * 136 + n]);
                mma8(acc[0][ni], a[0], b0, b1);
                mma8(acc[1][ni], a[1], b0, b1);
            }
        }
        __syncthreads();
    }
#pragma unroll
    for (int mi = 0; mi < 2; mi++)
#pragma unroll
        for (int ni = 0; ni < 8; ni++) {
            const int col = colBlk + wn + ni * 8 + 2 * t;
            const float bx = bias[col], by = bias[col + 1];
            const int r0 = rowBlk + wm + mi * 16 + g;
            float2 v0 = {acc[mi][ni][0] + bx, acc[mi][ni][1] + by};
            *(float2*)(C + (size_t)r0 * 512 + col) = v0;
            float2 v1 = {acc[mi][ni][2] + bx, acc[mi][ni][3] + by};
            *(float2*)(C + (size_t)(r0 + 8) * 512 + col) = v1;
        }
}

// ============================================================================
// fused attention, 512 threads (16 warps): scores -> spike softmax -> attn@V
// S tile [512 keys][72]; Q [64][68] (pre-converted tf32); K dbuf [2][64][68];
// V dbuf [2][64][72] (union with Q/K). dyn smem = 199680 B.
// Warp grid both phases: 4(M)x4(N), 16x16 warp tiles.
// grid = (8 qtiles, 256 p), block = 512.
// ============================================================================
#define FS_S_W   72
#define FS_QK_W  68
#define FS_KBUF  (64 * FS_QK_W)
#define FS_VBUF  (64 * FS_S_W)
#define FS_UOFF  147456            // byte offset of union region (512*72*4)
__global__ __launch_bounds__(512, 1) void fused_attn(
    const float* __restrict__ mw, const float* __restrict__ tsync,
    const int* __restrict__ qm, const int* __restrict__ km)
{
    extern __shared__ __align__(16) unsigned char smraw[];
    float*    Sf = (float*)smraw;                       // [512][72]
    uint32_t* Su = (uint32_t*)smraw;
    float*    Qs = (float*)(smraw + FS_UOFF);           // [64][68]
    uint32_t* QsU = (uint32_t*)Qs;
    float*    Ks = (float*)(smraw + FS_UOFF + 64 * FS_QK_W * 4);  // [2][64][68]
    float*    Vs = (float*)(smraw + FS_UOFF);           // [2][64][72] (union)
    const uint32_t sQ = (uint32_t)__cvta_generic_to_shared(Qs);
    const uint32_t sK = (uint32_t)__cvta_generic_to_shared(Ks);
    const uint32_t sV = (uint32_t)__cvta_generic_to_shared(Vs);

    const int tid = threadIdx.x;
    const int lane = tid & 31, warp = tid >> 5;
    const int g = lane >> 2, t = lane & 3;

    const int tile = blockIdx.x;
    const int p = blockIdx.y;
    const int h = p & 7;
    const int tt = (p >> 3) & 15;
    const int b = p >> 7;
    const size_t rowbase = ((size_t)(b * T_STEPS + tt) * SEQ);
    const float* Qg = g_Q + (rowbase + tile * 64) * 512 + h * HD;
    const float* Kg = g_K + rowbase * 512 + h * HD;
    const float* Vg = g_V + rowbase * 512 + h * HD;
    float*       Cg = g_att + (rowbase + tile * 64) * 512 + h * HD;

    const float alpha = 0.125f * mw[qm[0] * H_NUM + h] * mw[km[0] * H_NUM + h];
    const float sy = tsync[tt * H_NUM + h];

    // warp grid: 4(M)x4(N), 16x16 tiles
    const int wm = (warp >> 2) * 16;
    const int wn = (warp & 3) * 16;

    // ---- prologue: Q + K0 (group 1), K1 (group 2) ----
    {
#pragma unroll
        for (int i = 0; i < 2; i++) {
            int seg = i * 512 + tid;
            int r = seg >> 4, s = (seg & 15) << 2;
            cpa16(sQ + ((r * FS_QK_W + s) << 2), Qg + (size_t)r * 512 + s);
            cpa16(sK + ((r * FS_QK_W + s) << 2), Kg + (size_t)r * 512 + s);
        }
        cpa_commit();
#pragma unroll
        for (int i = 0; i < 2; i++) {
            int seg = i * 512 + tid;
            int r = seg >> 4, s = (seg & 15) << 2;
            cpa16(sK + ((FS_KBUF + r * FS_QK_W + s) << 2),
                  Kg + (size_t)(64 + r) * 512 + s);
        }
        cpa_commit();
    }
    cpa_wait1();               // Q + K0 landed
    __syncthreads();
    // convert Q in place to tf32 (64x64 data words, stride 68)
    {
        const int r = tid >> 3, c0 = (tid & 7) * 8;
        float4 v0 = *(float4*)(Qs + r * FS_QK_W + c0);
        float4 v1 = *(float4*)(Qs + r * FS_QK_W + c0 + 4);
        uint4 u0 = {f2tf(v0.x), f2tf(v0.y), f2tf(v0.z), f2tf(v0.w)};
        uint4 u1 = {f2tf(v1.x), f2tf(v1.y), f2tf(v1.z), f2tf(v1.w)};
        *(uint4*)(QsU + r * FS_QK_W + c0) = u0;
        *(uint4*)(QsU + r * FS_QK_W + c0 + 4) = u1;
    }
    __syncthreads();

    // ---- phase 1: scores into S (transposed: S[key][qrow]) ----
    for (int c = 0; c < 8; c++) {
        if (c < 7) cpa_wait1(); else cpa_wait0();   // K_c ready
        __syncthreads();
        const float* Kb = Ks + (c & 1) * FS_KBUF;
        float acc[2][4] = {};
#pragma unroll
        for (int ks = 0; ks < 8; ks++) {
            const int kc = ks * 8 + t;
            uint32_t a[4];
            a[0] = QsU[(wm + g) * FS_QK_W + kc];
            a[1] = QsU[(wm + 8 + g) * FS_QK_W + kc];
            a[2] = QsU[(wm + g) * FS_QK_W + kc + 4];
            a[3] = QsU[(wm + 8 + g) * FS_QK_W + kc + 4];
#pragma unroll
            for (int ni = 0; ni < 2; ni++) {
                const int n = wn + ni * 8 + g;
                uint32_t b0 = f2tf(Kb[n * FS_QK_W + kc]);
                uint32_t b1 = f2tf(Kb[n * FS_QK_W + kc + 4]);
                mma8(acc[ni], a, b0, b1);
            }
        }
#pragma unroll
        for (int ni = 0; ni < 2; ni++) {
            const int n0 = c * 64 + wn + ni * 8 + 2 * t;
            const int r0 = wm + g;
            Sf[n0 * FS_S_W + r0]           = acc[ni][0] * alpha + sy;
            Sf[(n0 + 1) * FS_S_W + r0]     = acc[ni][1] * alpha + sy;
            Sf[n0 * FS_S_W + r0 + 8]       = acc[ni][2] * alpha + sy;
            Sf[(n0 + 1) * FS_S_W + r0 + 8] = acc[ni][3] * alpha + sy;
        }
        __syncthreads();
        if (c + 2 < 8) {   // refill freed K buffer
            const int buf = c & 1;
#pragma unroll
            for (int i = 0; i < 2; i++) {
                int seg = i * 512 + tid;
                int r = seg >> 4, s = (seg & 15) << 2;
                cpa16(sK + ((buf * FS_KBUF + r * FS_QK_W + s) << 2),
                      Kg + (size_t)((c + 2) * 64 + r) * 512 + s);
            }
            cpa_commit();
        }
    }

    // ---- prefetch V chunks 0,1 (union region; phase-1 reads done) ----
#pragma unroll
    for (int cc = 0; cc < 2; cc++) {
#pragma unroll
        for (int i = 0; i < 2; i++) {
            int seg = i * 512 + tid;
            int r = seg >> 4, s = (seg & 15) << 2;
            cpa16(sV + ((cc * FS_VBUF + r * FS_S_W + s) << 2),
                  Vg + (size_t)(cc * 64 + r) * 512 + s);
        }
        cpa_commit();
    }

    // ---- spike softmax: 16 warps x 4 rows, 8 threads per row ----
    {
        const int mrow = warp * 4 + (lane >> 3);
        const int np = lane & 7;
        float mx = -1e30f;
#pragma unroll 8
        for (int ci = 0; ci < 64; ci++)
            mx = fmaxf(mx, Sf[(np + 8 * ci) * FS_S_W + mrow]);
        mx = fmaxf(mx, __shfl_xor_sync(0xFFFFFFFFu, mx, 1));
        mx = fmaxf(mx, __shfl_xor_sync(0xFFFFFFFFu, mx, 2));
        mx = fmaxf(mx, __shfl_xor_sync(0xFFFFFFFFu, mx, 4));
        float sum = 0.f;
#pragma unroll 8
        for (int ci = 0; ci < 64; ci++) {
            const int idx = (np + 8 * ci) * FS_S_W + mrow;
            float pv = 1.f / (1.f + __expf(-5.f * (Sf[idx] - mx)));
            Sf[idx] = pv;
            sum += pv;
        }
        sum += __shfl_xor_sync(0xFFFFFFFFu, sum, 1);
        sum += __shfl_xor_sync(0xFFFFFFFFu, sum, 2);
        sum += __shfl_xor_sync(0xFFFFFFFFu, sum, 4);
        const float inv = 1.f / (sum + 1e-8f);
#pragma unroll 8
        for (int ci = 0; ci < 64; ci++) {
            const int idx = (np + 8 * ci) * FS_S_W + mrow;
            Su[idx] = f2tf(Sf[idx] * inv);
        }
    }
    __syncthreads();

    // ---- phase 2: O = attn @ V ----
    float acc2[2][4] = {};
    for (int c = 0; c < 8; c++) {
        if (c < 7) cpa_wait1(); else cpa_wait0();
        __syncthreads();
        const float* Vb = Vs + (c & 1) * FS_VBUF;
#pragma unroll
        for (int ks = 0; ks < 8; ks++) {
            const int kl = ks * 8 + t;
            const int kg = c * 64 + kl;
            uint32_t a[4];
            a[0] = Su[kg * FS_S_W + wm + g];
            a[1] = Su[kg * FS_S_W + wm + 8 + g];
            a[2] = Su[(kg + 4) * FS_S_W + wm + g];
            a[3] = Su[(kg + 4) * FS_S_W + wm + 8 + g];
#pragma unroll
            for (int ni = 0; ni < 2; ni++) {
                const int n = wn + ni * 8 + g;
                uint32_t b0 = f2tf(Vb[kl * FS_S_W + n]);
                uint32_t b1 = f2tf(Vb[(kl + 4) * FS_S_W + n]);
                mma8(acc2[ni], a, b0, b1);
            }
        }
        __syncthreads();
        if (c + 2 < 8) {
            const int buf = c & 1;
#pragma unroll
            for (int i = 0; i < 2; i++) {
                int seg = i * 512 + tid;
                int r = seg >> 4, s = (seg & 15) << 2;
                cpa16(sV + ((buf * FS_VBUF + r * FS_S_W + s) << 2),
                      Vg + (size_t)((c + 2) * 64 + r) * 512 + s);
            }
            cpa_commit();
        }
    }
#pragma unroll
    for (int ni = 0; ni < 2; ni++) {
        const int col = wn + ni * 8 + 2 * t;
        const int r0 = wm + g;
        float2 v0 = {acc2[ni][0], acc2[ni][1]};
        *(float2*)(Cg + (size_t)r0 * 512 + col) = v0;
        float2 v1 = {acc2[ni][2], acc2[ni][3]};
        *(float2*)(Cg + (size_t)(r0 + 8) * 512 + col) = v1;
    }
}

// ============================================================================
// launch
// ============================================================================
#define PJ_SMEM 71680
#define FS_SMEM 199680
extern "C" void kernel_launch(void* const* d_in, const int* in_sizes, int n_in,
                              void* d_out, int out_size)
{
    const float* q_sp = (const float*)d_in[0];
    const float* k_sp = (const float*)d_in[1];
    const float* v_sp = (const float*)d_in[2];
    const float* Wq = (const float*)d_in[3];  const float* bq = (const float*)d_in[4];
    const float* Wk = (const float*)d_in[5];  const float* bk = (const float*)d_in[6];
    const float* Wv = (const float*)d_in[7];  const float* bv = (const float*)d_in[8];
    const float* Wo = (const float*)d_in[9];  const float* bo = (const float*)d_in[10];
    const float* mw    = (const float*)d_in[11];
    const float* tsync = (const float*)d_in[12];
    const int* qm = (const int*)d_in[13];
    const int* km = (const int*)d_in[14];
    float* out = (float*)d_out;

    // unconditional (no static guards): idempotent, not stream-ordered
    cudaFuncSetAttribute(proj3_gemm, cudaFuncAttributeMaxDynamicSharedMemorySize, PJ_SMEM);
    cudaFuncSetAttribute(fused_attn, cudaFuncAttributeMaxDynamicSharedMemorySize, FS_SMEM);

    float *dQ, *dK, *dV, *dAtt;
    cudaGetSymbolAddress((void**)&dQ, g_Q);
    cudaGetSymbolAddress((void**)&dK, g_K);
    cudaGetSymbolAddress((void**)&dV, g_V);
    cudaGetSymbolAddress((void**)&dAtt, g_att);

    // Q, K, V projections in one launch
    proj3_gemm<<<dim3(D_EMB / 128, M_ROWS / 128, 3), 256, PJ_SMEM>>>(
        q_sp, Wq, bq, dQ,
        k_sp, Wk, bk, dK,
        v_sp, Wv, bv, dV);

    fused_attn<<<dim3(SEQ / 64, PBATCH), 512, FS_SMEM>>>(mw, tsync, qm, km);

    // output projection
    proj3_gemm<<<dim3(D_EMB / 128, M_ROWS / 128, 1), 256, PJ_SMEM>>>(
        dAtt, Wo, bo, out,
        dAtt, Wo, bo, out,
        dAtt, Wo, bo, out);
}

// round 8
// speedup vs baseline: 2.7477x; 1.2017x over previous
#include <cuda_runtime.h>
#include <stdint.h>

#define D_EMB   512
#define H_NUM   8
#define T_STEPS 16
#define NB      2
#define SEQ     512
#define HD      64
#define M_ROWS  (NB * T_STEPS * SEQ)      // 16384
#define PBATCH  (NB * T_STEPS * H_NUM)    // 256

// ---- scratch ----
__device__ float g_Q[(size_t)M_ROWS * D_EMB];
__device__ float g_K[(size_t)M_ROWS * D_EMB];
__device__ float g_V[(size_t)M_ROWS * D_EMB];
__device__ float g_att[(size_t)M_ROWS * D_EMB];

// ---- helpers ----
__device__ __forceinline__ uint32_t f2tf(float x) {
    uint32_t r;
    asm("cvt.rna.tf32.f32 %0, %1;" : "=r"(r) : "f"(x));
    return r;
}
__device__ __forceinline__ void mma8(float* c, const uint32_t* a, uint32_t b0, uint32_t b1) {
    asm volatile(
        "mma.sync.aligned.m16n8k8.row.col.f32.tf32.tf32.f32 "
        "{%0,%1,%2,%3}, {%4,%5,%6,%7}, {%8,%9}, {%0,%1,%2,%3};"
        : "+f"(c[0]), "+f"(c[1]), "+f"(c[2]), "+f"(c[3])
        : "r"(a[0]), "r"(a[1]), "r"(a[2]), "r"(a[3]), "r"(b0), "r"(b1));
}
__device__ __forceinline__ void cpa16(uint32_t dst, const void* src) {
    asm volatile("cp.async.ca.shared.global [%0], [%1], 16;" :: "r"(dst), "l"(src));
}
__device__ __forceinline__ void cpa_commit() { asm volatile("cp.async.commit_group;"); }
__device__ __forceinline__ void cpa_wait1() { asm volatile("cp.async.wait_group 1;"); }
__device__ __forceinline__ void cpa_wait0() { asm volatile("cp.async.wait_group 0;"); }

// ============================================================================
// merged projection GEMM: z selects (A,W,bias,C) triple.
// ============================================================================
#define PJ_AS_W 4608
#define PJ_WS_W 4352
__global__ __launch_bounds__(256, 2) void proj3_gemm(
    const float* __restrict__ A0, const float* __restrict__ W0,
    const float* __restrict__ B0, float* __restrict__ C0,
    const float* __restrict__ A1, const float* __restrict__ W1,
    const float* __restrict__ B1, float* __restrict__ C1,
    const float* __restrict__ A2, const float* __restrict__ W2,
    const float* __restrict__ B2, float* __restrict__ C2)
{
    const int z = blockIdx.z;
    const float* A    = (z == 0) ? A0 : (z == 1) ? A1 : A2;
    const float* W    = (z == 0) ? W0 : (z == 1) ? W1 : W2;
    const float* bias = (z == 0) ? B0 : (z == 1) ? B1 : B2;
    float*       C    = (z == 0) ? C0 : (z == 1) ? C1 : C2;

    extern __shared__ __align__(16) unsigned char smraw[];
    float* As = (float*)smraw;
    float* Ws = (float*)(smraw + 2 * PJ_AS_W * 4);
    const uint32_t sAs = (uint32_t)__cvta_generic_to_shared(As);
    const uint32_t sWs = (uint32_t)__cvta_generic_to_shared(Ws);

    const int tid = threadIdx.x;
    const int lane = tid & 31, warp = tid >> 5;
    const int g = lane >> 2, t = lane & 3;
    const int wm = (warp >> 1) * 32;
    const int wn = (warp & 1) * 64;
    const int rowBlk = blockIdx.y * 128;
    const int colBlk = blockIdx.x * 128;

    auto issue = [&](int st) {
        const int buf = st & 1;
        const int k0 = st * 32;
#pragma unroll
        for (int i = 0; i < 4; i++) {
            int seg = i * 256 + tid;
            int r = seg >> 3, s = (seg & 7) << 2;
            cpa16(sAs + ((buf * PJ_AS_W + r * 36 + s) << 2),
                  A + (size_t)(rowBlk + r) * 512 + k0 + s);
        }
#pragma unroll
        for (int i = 0; i < 4; i++) {
            int seg = i * 256 + tid;
            int kr = seg >> 5, s = (seg & 31) << 2;
            cpa16(sWs + ((buf * PJ_WS_W + kr * 136 + s) << 2),
                  W + (size_t)(k0 + kr) * 512 + colBlk + s);
        }
        cpa_commit();
    };

    float acc[2][8][4] = {};
    issue(0);
    for (int st = 0; st < 16; st++) {
        if (st + 1 < 16) { issue(st + 1); cpa_wait1(); } else cpa_wait0();
        __syncthreads();
        const float* Ab = As + (st & 1) * PJ_AS_W;
        const float* Wb = Ws + (st & 1) * PJ_WS_W;
#pragma unroll
        for (int ks = 0; ks < 4; ks++) {
            const int kc = ks * 8 + t;
            uint32_t a[2][4];
#pragma unroll
            for (int mi = 0; mi < 2; mi++) {
                const int m = wm + mi * 16 + g;
                a[mi][0] = f2tf(Ab[m * 36 + kc]);
                a[mi][1] = f2tf(Ab[(m + 8) * 36 + kc]);
                a[mi][2] = f2tf(Ab[m * 36 + kc + 4]);
                a[mi][3] = f2tf(Ab[(m + 8) * 36 + kc + 4]);
            }
#pragma unroll
            for (int ni = 0; ni < 8; ni++) {
                const int n = wn + ni * 8 + g;
                uint32_t b0 = f2tf(Wb[kc * 136 + n]);
                uint32_t b1 = f2tf(Wb[(kc + 4) * 136 + n]);
                mma8(acc[0][ni], a[0], b0, b1);
                mma8(acc[1][ni], a[1], b0, b1);
            }
        }
        __syncthreads();
    }
#pragma unroll
    for (int mi = 0; mi < 2; mi++)
#pragma unroll
        for (int ni = 0; ni < 8; ni++) {
            const int col = colBlk + wn + ni * 8 + 2 * t;
            const float bx = bias[col], by = bias[col + 1];
            const int r0 = rowBlk + wm + mi * 16 + g;
            float2 v0 = {acc[mi][ni][0] + bx, acc[mi][ni][1] + by};
            *(float2*)(C + (size_t)r0 * 512 + col) = v0;
            float2 v1 = {acc[mi][ni][2] + bx, acc[mi][ni][3] + by};
            *(float2*)(C + (size_t)(r0 + 8) * 512 + col) = v1;
        }
}

// ============================================================================
// fused attention, register-resident scores. 512 threads (16 warps, 4Mx4N).
// Per (p, qtile64): phase1 scores -> regs (64/thread, key-permuted so the
// C-fragment IS the phase-2 A-fragment) -> register softmax (shfl + 1KB
// stats) -> phase2 partial O per warp over its own 128 keys -> 4-way smem
// reduce. smem: Q[64][68] + K dbuf 2x[64][68] + V dbuf 2x[64][72] + stats;
// Opart[16][16][68] overlays dead Q/K/V-buf0. dyn smem = 90112 B.
// grid = (8 qtiles, 256 p), block = 512.
// ============================================================================
#define FA_QK_W  68
#define FA_V_W   72
#define FA_KBUF  (64 * FA_QK_W)
#define FA_VBUF  (64 * FA_V_W)
#define FA_QOFF  0
#define FA_KOFF  17408                  // 64*68*4
#define FA_VOFF  52224                  // FA_KOFF + 2*64*68*4
#define FA_STAT  89088                  // FA_VOFF + 2*64*72*4
#define FA_SMEM  90112                  // + 64*4*4
__global__ __launch_bounds__(512, 1) void fused_attn(
    const float* __restrict__ mw, const float* __restrict__ tsync,
    const int* __restrict__ qm, const int* __restrict__ km)
{
    extern __shared__ __align__(16) unsigned char smraw[];
    float* Qs    = (float*)(smraw + FA_QOFF);     // [64][68]
    float* Ks    = (float*)(smraw + FA_KOFF);     // [2][64][68]
    float* Vs    = (float*)(smraw + FA_VOFF);     // [2][64][72]
    float* stats = (float*)(smraw + FA_STAT);     // [64][4]
    float* Opart = (float*)smraw;                 // [16][16][68] overlay
    const uint32_t sQ = (uint32_t)__cvta_generic_to_shared(Qs);
    const uint32_t sK = (uint32_t)__cvta_generic_to_shared(Ks);
    const uint32_t sV = (uint32_t)__cvta_generic_to_shared(Vs);

    const int tid = threadIdx.x;
    const int lane = tid & 31, warp = tid >> 5;
    const int g = lane >> 2, t = lane & 3;
    const int wm = (warp >> 2) * 16;     // M group (q rows)
    const int wni = warp & 3;            // key-slice / reduce slot
    const int wn = wni * 16;
    const int sig = (g >> 1) + ((g & 1) << 2);   // column permutation

    const int tile = blockIdx.x;
    const int p = blockIdx.y;
    const int h = p & 7;
    const int tt = (p >> 3) & 15;
    const int b = p >> 7;
    const size_t rowbase = ((size_t)(b * T_STEPS + tt) * SEQ);
    const float* Qg = g_Q + (rowbase + tile * 64) * 512 + h * HD;
    const float* Kg = g_K + rowbase * 512 + h * HD;
    const float* Vg = g_V + rowbase * 512 + h * HD;
    float*       Cg = g_att + (rowbase + tile * 64) * 512 + h * HD;

    const float alpha = 0.125f * mw[qm[0] * H_NUM + h] * mw[km[0] * H_NUM + h];
    const float sy = tsync[tt * H_NUM + h];

    // ---- prologue: {Q + K0} group, {K1} group ----
#pragma unroll
    for (int i = 0; i < 2; i++) {
        int seg = i * 512 + tid;
        int r = seg >> 4, s = (seg & 15) << 2;
        cpa16(sQ + ((r * FA_QK_W + s) << 2), Qg + (size_t)r * 512 + s);
        cpa16(sK + ((r * FA_QK_W + s) << 2), Kg + (size_t)r * 512 + s);
    }
    cpa_commit();
#pragma unroll
    for (int i = 0; i < 2; i++) {
        int seg = i * 512 + tid;
        int r = seg >> 4, s = (seg & 15) << 2;
        cpa16(sK + ((FA_KBUF + r * FA_QK_W + s) << 2),
              Kg + (size_t)(64 + r) * 512 + s);
    }
    cpa_commit();
    cpa_wait1();                 // Q + K0 landed
    __syncthreads();

    // ---- preload Q a-fragments to registers (reused by all 8 chunks) ----
    uint32_t Qf[8][4];
#pragma unroll
    for (int ks = 0; ks < 8; ks++) {
        const int kc = ks * 8 + t;
        Qf[ks][0] = f2tf(Qs[(wm + g) * FA_QK_W + kc]);
        Qf[ks][1] = f2tf(Qs[(wm + 8 + g) * FA_QK_W + kc]);
        Qf[ks][2] = f2tf(Qs[(wm + g) * FA_QK_W + kc + 4]);
        Qf[ks][3] = f2tf(Qs[(wm + 8 + g) * FA_QK_W + kc + 4]);
    }

    // ---- phase 1: scores into registers ----
    float accS[8][2][4] = {};
#pragma unroll
    for (int c = 0; c < 8; c++) {
        if (c < 7) cpa_wait1(); else cpa_wait0();
        __syncthreads();
        const float* Kb = Ks + (c & 1) * FA_KBUF;
#pragma unroll
        for (int ks = 0; ks < 8; ks++) {
            const int kc = ks * 8 + t;
#pragma unroll
            for (int kt = 0; kt < 2; kt++) {
                const int n = wn + kt * 8 + sig;   // sigma-permuted key row
                uint32_t b0 = f2tf(Kb[n * FA_QK_W + kc]);
                uint32_t b1 = f2tf(Kb[n * FA_QK_W + kc + 4]);
                mma8(accS[c][kt], Qf[ks], b0, b1);
            }
        }
        __syncthreads();
        if (c + 2 < 8) {         // refill freed K buffer
            const int buf = c & 1;
#pragma unroll
            for (int i = 0; i < 2; i++) {
                int seg = i * 512 + tid;
                int r = seg >> 4, s = (seg & 15) << 2;
                cpa16(sK + ((buf * FA_KBUF + r * FA_QK_W + s) << 2),
                      Kg + (size_t)((c + 2) * 64 + r) * 512 + s);
            }
            cpa_commit();
        }
    }

    // ---- prefetch V chunks 0,1 (overlaps softmax) ----
#pragma unroll
    for (int cc = 0; cc < 2; cc++) {
#pragma unroll
        for (int i = 0; i < 2; i++) {
            int seg = i * 512 + tid;
            int r = seg >> 4, s = (seg & 15) << 2;
            cpa16(sV + ((cc * FA_VBUF + r * FA_V_W + s) << 2),
                  Vg + (size_t)(cc * 64 + r) * 512 + s);
        }
        cpa_commit();
    }

    // ---- register softmax ----
    {
        float* aS = &accS[0][0][0];
#pragma unroll
        for (int i = 0; i < 64; i++) aS[i] = aS[i] * alpha + sy;

        float m0 = -1e30f, m1 = -1e30f;
#pragma unroll
        for (int i = 0; i < 64; i += 4) {
            m0 = fmaxf(m0, fmaxf(aS[i], aS[i + 1]));
            m1 = fmaxf(m1, fmaxf(aS[i + 2], aS[i + 3]));
        }
        m0 = fmaxf(m0, __shfl_xor_sync(0xFFFFFFFFu, m0, 1));
        m0 = fmaxf(m0, __shfl_xor_sync(0xFFFFFFFFu, m0, 2));
        m1 = fmaxf(m1, __shfl_xor_sync(0xFFFFFFFFu, m1, 1));
        m1 = fmaxf(m1, __shfl_xor_sync(0xFFFFFFFFu, m1, 2));
        if (t == 0) {
            stats[(wm + g) * 4 + wni] = m0;
            stats[(wm + 8 + g) * 4 + wni] = m1;
        }
        __syncthreads();
        {
            float4 v0 = *(float4*)&stats[(wm + g) * 4];
            m0 = fmaxf(fmaxf(v0.x, v0.y), fmaxf(v0.z, v0.w));
            float4 v1 = *(float4*)&stats[(wm + 8 + g) * 4];
            m1 = fmaxf(fmaxf(v1.x, v1.y), fmaxf(v1.z, v1.w));
        }
        __syncthreads();

        float s0 = 0.f, s1 = 0.f;
#pragma unroll
        for (int i = 0; i < 64; i += 4) {
            float p0 = 1.f / (1.f + __expf(-5.f * (aS[i]     - m0)));
            float p1 = 1.f / (1.f + __expf(-5.f * (aS[i + 1] - m0)));
            float p2 = 1.f / (1.f + __expf(-5.f * (aS[i + 2] - m1)));
            float p3 = 1.f / (1.f + __expf(-5.f * (aS[i + 3] - m1)));
            aS[i] = p0; aS[i + 1] = p1; aS[i + 2] = p2; aS[i + 3] = p3;
            s0 += p0 + p1; s1 += p2 + p3;
        }
        s0 += __shfl_xor_sync(0xFFFFFFFFu, s0, 1);
        s0 += __shfl_xor_sync(0xFFFFFFFFu, s0, 2);
        s1 += __shfl_xor_sync(0xFFFFFFFFu, s1, 1);
        s1 += __shfl_xor_sync(0xFFFFFFFFu, s1, 2);
        if (t == 0) {
            stats[(wm + g) * 4 + wni] = s0;
            stats[(wm + 8 + g) * 4 + wni] = s1;
        }
        __syncthreads();
        {
            float4 v0 = *(float4*)&stats[(wm + g) * 4];
            s0 = v0.x + v0.y + v0.z + v0.w;
            float4 v1 = *(float4*)&stats[(wm + 8 + g) * 4];
            s1 = v1.x + v1.y + v1.z + v1.w;
        }
        const float inv0 = 1.f / (s0 + 1e-8f);
        const float inv1 = 1.f / (s1 + 1e-8f);
#pragma unroll
        for (int i = 0; i < 64; i += 4) {
            aS[i]     = __uint_as_float(f2tf(aS[i]     * inv0));
            aS[i + 1] = __uint_as_float(f2tf(aS[i + 1] * inv0));
            aS[i + 2] = __uint_as_float(f2tf(aS[i + 2] * inv1));
            aS[i + 3] = __uint_as_float(f2tf(aS[i + 3] * inv1));
        }
    }

    // ---- phase 2: partial O over this warp's 128 keys ----
    float acc2[8][4] = {};
#pragma unroll
    for (int c = 0; c < 8; c++) {
        if (c < 7) cpa_wait1(); else cpa_wait0();
        __syncthreads();
        const float* Vb = Vs + (c & 1) * FA_VBUF;
#pragma unroll
        for (int kt = 0; kt < 2; kt++) {
            uint32_t a[4];
            a[0] = __float_as_uint(accS[c][kt][0]);
            a[1] = __float_as_uint(accS[c][kt][2]);
            a[2] = __float_as_uint(accS[c][kt][1]);
            a[3] = __float_as_uint(accS[c][kt][3]);
            const int klb = wn + kt * 8 + t;
#pragma unroll
            for (int ci = 0; ci < 8; ci++) {
                const int n = ci * 8 + g;
                uint32_t b0 = f2tf(Vb[klb * FA_V_W + n]);
                uint32_t b1 = f2tf(Vb[(klb + 4) * FA_V_W + n]);
                mma8(acc2[ci], a, b0, b1);
            }
        }
        __syncthreads();
        if (c + 2 < 8) {
            const int buf = c & 1;
#pragma unroll
            for (int i = 0; i < 2; i++) {
                int seg = i * 512 + tid;
                int r = seg >> 4, s = (seg & 15) << 2;
                cpa16(sV + ((buf * FA_VBUF + r * FA_V_W + s) << 2),
                      Vg + (size_t)((c + 2) * 64 + r) * 512 + s);
            }
            cpa_commit();
        }
    }

    // ---- epilogue: store partials, 4-way reduce, STG ----
    {
        const int opb = warp * 1088;     // 16*68 words per warp
#pragma unroll
        for (int ci = 0; ci < 8; ci++) {
            float2 v0 = {acc2[ci][0], acc2[ci][1]};
            *(float2*)&Opart[opb + g * FA_QK_W + ci * 8 + 2 * t] = v0;
            float2 v1 = {acc2[ci][2], acc2[ci][3]};
            *(float2*)&Opart[opb + (g + 8) * FA_QK_W + ci * 8 + 2 * t] = v1;
        }
    }
    __syncthreads();
    {
        const int rr = tid >> 3;            // 0..63
        const int c8 = (tid & 7) * 8;       // 0..56
        float4 o0 = {0.f, 0.f, 0.f, 0.f}, o1 = {0.f, 0.f, 0.f, 0.f};
#pragma unroll
        for (int wv = 0; wv < 4; wv++) {
            const float* src = Opart + ((rr >> 4) * 4 + wv) * 1088
                             + (rr & 15) * FA_QK_W + c8;
            float4 x0 = *(const float4*)src;
            float4 x1 = *(const float4*)(src + 4);
            o0.x += x0.x; o0.y += x0.y; o0.z += x0.z; o0.w += x0.w;
            o1.x += x1.x; o1.y += x1.y; o1.z += x1.z; o1.w += x1.w;
        }
        *(float4*)(Cg + (size_t)rr * 512 + c8) = o0;
        *(float4*)(Cg + (size_t)rr * 512 + c8 + 4) = o1;
    }
}

// ============================================================================
// launch
// ============================================================================
#define PJ_SMEM 71680
extern "C" void kernel_launch(void* const* d_in, const int* in_sizes, int n_in,
                              void* d_out, int out_size)
{
    const float* q_sp = (const float*)d_in[0];
    const float* k_sp = (const float*)d_in[1];
    const float* v_sp = (const float*)d_in[2];
    const float* Wq = (const float*)d_in[3];  const float* bq = (const float*)d_in[4];
    const float* Wk = (const float*)d_in[5];  const float* bk = (const float*)d_in[6];
    const float* Wv = (const float*)d_in[7];  const float* bv = (const float*)d_in[8];
    const float* Wo = (const float*)d_in[9];  const float* bo = (const float*)d_in[10];
    const float* mw    = (const float*)d_in[11];
    const float* tsync = (const float*)d_in[12];
    const int* qm = (const int*)d_in[13];
    const int* km = (const int*)d_in[14];
    float* out = (float*)d_out;

    // unconditional (no static guards): idempotent, not stream-ordered
    cudaFuncSetAttribute(proj3_gemm, cudaFuncAttributeMaxDynamicSharedMemorySize, PJ_SMEM);
    cudaFuncSetAttribute(fused_attn, cudaFuncAttributeMaxDynamicSharedMemorySize, FA_SMEM);

    float *dQ, *dK, *dV, *dAtt;
    cudaGetSymbolAddress((void**)&dQ, g_Q);
    cudaGetSymbolAddress((void**)&dK, g_K);
    cudaGetSymbolAddress((void**)&dV, g_V);
    cudaGetSymbolAddress((void**)&dAtt, g_att);

    // Q, K, V projections in one launch
    proj3_gemm<<<dim3(D_EMB / 128, M_ROWS / 128, 3), 256, PJ_SMEM>>>(
        q_sp, Wq, bq, dQ,
        k_sp, Wk, bk, dK,
        v_sp, Wv, bv, dV);

    fused_attn<<<dim3(SEQ / 64, PBATCH), 512, FA_SMEM>>>(mw, tsync, qm, km);

    // output projection
    proj3_gemm<<<dim3(D_EMB / 128, M_ROWS / 128, 1), 256, PJ_SMEM>>>(
        dAtt, Wo, bo, out,
        dAtt, Wo, bo, out,
        dAtt, Wo, bo, out);
}

// round 11
// speedup vs baseline: 2.8105x; 1.0228x over previous
#include <cuda_runtime.h>
#include <stdint.h>

#define D_EMB   512
#define H_NUM   8
#define T_STEPS 16
#define NB      2
#define SEQ     512
#define HD      64
#define M_ROWS  (NB * T_STEPS * SEQ)      // 16384
#define PBATCH  (NB * T_STEPS * H_NUM)    // 256

// ---- scratch ----
__device__ float g_Q[(size_t)M_ROWS * D_EMB];
__device__ float g_K[(size_t)M_ROWS * D_EMB];
__device__ float g_V[(size_t)M_ROWS * D_EMB];
__device__ float g_att[(size_t)M_ROWS * D_EMB];

// ---- helpers ----
__device__ __forceinline__ uint32_t f2tf(float x) {
    uint32_t r;
    asm("cvt.rna.tf32.f32 %0, %1;" : "=r"(r) : "f"(x));
    return r;
}
__device__ __forceinline__ void mma8(float* c, const uint32_t* a, uint32_t b0, uint32_t b1) {
    asm volatile(
        "mma.sync.aligned.m16n8k8.row.col.f32.tf32.tf32.f32 "
        "{%0,%1,%2,%3}, {%4,%5,%6,%7}, {%8,%9}, {%0,%1,%2,%3};"
        : "+f"(c[0]), "+f"(c[1]), "+f"(c[2]), "+f"(c[3])
        : "r"(a[0]), "r"(a[1]), "r"(a[2]), "r"(a[3]), "r"(b0), "r"(b1));
}
__device__ __forceinline__ void cpa16(uint32_t dst, const void* src) {
    asm volatile("cp.async.ca.shared.global [%0], [%1], 16;" :: "r"(dst), "l"(src));
}
__device__ __forceinline__ void cpa_commit() { asm volatile("cp.async.commit_group;"); }
__device__ __forceinline__ void cpa_wait1() { asm volatile("cp.async.wait_group 1;"); }
__device__ __forceinline__ void cpa_wait0() { asm volatile("cp.async.wait_group 0;"); }

// ============================================================================
// merged projection GEMM (R8 form: float W, in-loop cvt): z selects triple.
// roundC!=0: tf32-round outputs (so fused_attn can load raw).
// ============================================================================
#define PJ_AS_W 4608
#define PJ_WS_W 4352
__global__ __launch_bounds__(256, 2) void proj3_gemm(
    const float* __restrict__ A0, const float* __restrict__ W0,
    const float* __restrict__ B0, float* __restrict__ C0,
    const float* __restrict__ A1, const float* __restrict__ W1,
    const float* __restrict__ B1, float* __restrict__ C1,
    const float* __restrict__ A2, const float* __restrict__ W2,
    const float* __restrict__ B2, float* __restrict__ C2,
    int roundC)
{
    const int z = blockIdx.z;
    const float* A    = (z == 0) ? A0 : (z == 1) ? A1 : A2;
    const float* W    = (z == 0) ? W0 : (z == 1) ? W1 : W2;
    const float* bias = (z == 0) ? B0 : (z == 1) ? B1 : B2;
    float*       C    = (z == 0) ? C0 : (z == 1) ? C1 : C2;

    extern __shared__ __align__(16) unsigned char smraw[];
    float* As = (float*)smraw;
    float* Ws = (float*)(smraw + 2 * PJ_AS_W * 4);
    const uint32_t sAs = (uint32_t)__cvta_generic_to_shared(As);
    const uint32_t sWs = (uint32_t)__cvta_generic_to_shared(Ws);

    const int tid = threadIdx.x;
    const int lane = tid & 31, warp = tid >> 5;
    const int g = lane >> 2, t = lane & 3;
    const int wm = (warp >> 1) * 32;
    const int wn = (warp & 1) * 64;
    const int rowBlk = blockIdx.y * 128;
    const int colBlk = blockIdx.x * 128;

    auto issue = [&](int st) {
        const int buf = st & 1;
        const int k0 = st * 32;
#pragma unroll
        for (int i = 0; i < 4; i++) {
            int seg = i * 256 + tid;
            int r = seg >> 3, s = (seg & 7) << 2;
            cpa16(sAs + ((buf * PJ_AS_W + r * 36 + s) << 2),
                  A + (size_t)(rowBlk + r) * 512 + k0 + s);
        }
#pragma unroll
        for (int i = 0; i < 4; i++) {
            int seg = i * 256 + tid;
            int kr = seg >> 5, s = (seg & 31) << 2;
            cpa16(sWs + ((buf * PJ_WS_W + kr * 136 + s) << 2),
                  W + (size_t)(k0 + kr) * 512 + colBlk + s);
        }
        cpa_commit();
    };

    float acc[2][8][4] = {};
    issue(0);
    for (int st = 0; st < 16; st++) {
        if (st + 1 < 16) { issue(st + 1); cpa_wait1(); } else cpa_wait0();
        __syncthreads();
        const float* Ab = As + (st & 1) * PJ_AS_W;
        const float* Wb = Ws + (st & 1) * PJ_WS_W;
#pragma unroll
        for (int ks = 0; ks < 4; ks++) {
            const int kc = ks * 8 + t;
            uint32_t a[2][4];
#pragma unroll
            for (int mi = 0; mi < 2; mi++) {
                const int m = wm + mi * 16 + g;
                a[mi][0] = f2tf(Ab[m * 36 + kc]);
                a[mi][1] = f2tf(Ab[(m + 8) * 36 + kc]);
                a[mi][2] = f2tf(Ab[m * 36 + kc + 4]);
                a[mi][3] = f2tf(Ab[(m + 8) * 36 + kc + 4]);
            }
#pragma unroll
            for (int ni = 0; ni < 8; ni++) {
                const int n = wn + ni * 8 + g;
                uint32_t b0 = f2tf(Wb[kc * 136 + n]);
                uint32_t b1 = f2tf(Wb[(kc + 4) * 136 + n]);
                mma8(acc[0][ni], a[0], b0, b1);
                mma8(acc[1][ni], a[1], b0, b1);
            }
        }
        __syncthreads();
    }
#pragma unroll
    for (int mi = 0; mi < 2; mi++)
#pragma unroll
        for (int ni = 0; ni < 8; ni++) {
            const int col = colBlk + wn + ni * 8 + 2 * t;
            const float bx = bias[col], by = bias[col + 1];
            const int r0 = rowBlk + wm + mi * 16 + g;
            float2 v0 = {acc[mi][ni][0] + bx, acc[mi][ni][1] + by};
            float2 v1 = {acc[mi][ni][2] + bx, acc[mi][ni][3] + by};
            if (roundC) {
                v0.x = __uint_as_float(f2tf(v0.x)); v0.y = __uint_as_float(f2tf(v0.y));
                v1.x = __uint_as_float(f2tf(v1.x)); v1.y = __uint_as_float(f2tf(v1.y));
            }
            *(float2*)(C + (size_t)r0 * 512 + col) = v0;
            *(float2*)(C + (size_t)(r0 + 8) * 512 + col) = v1;
        }
}

// ============================================================================
// fused attention, register-resident scores. Q/K/V arrive tf32-pre-rounded,
// so all hot-loop operand loads are raw (zero cvt). 512 threads (16 warps).
// ============================================================================
#define FA_QK_W  68
#define FA_V_W   72
#define FA_KBUF  (64 * FA_QK_W)
#define FA_VBUF  (64 * FA_V_W)
#define FA_QOFF  0
#define FA_KOFF  17408
#define FA_VOFF  52224
#define FA_STAT  89088
#define FA_SMEM  90112
__global__ __launch_bounds__(512, 1) void fused_attn(
    const float* __restrict__ mw, const float* __restrict__ tsync,
    const int* __restrict__ qm, const int* __restrict__ km)
{
    extern __shared__ __align__(16) unsigned char smraw[];
    uint32_t* Qs    = (uint32_t*)(smraw + FA_QOFF);   // [64][68]
    uint32_t* Ks    = (uint32_t*)(smraw + FA_KOFF);   // [2][64][68]
    uint32_t* Vs    = (uint32_t*)(smraw + FA_VOFF);   // [2][64][72]
    float*    stats = (float*)(smraw + FA_STAT);      // [64][4]
    float*    Opart = (float*)smraw;                  // [16][16][68] overlay
    const uint32_t sQ = (uint32_t)__cvta_generic_to_shared(Qs);
    const uint32_t sK = (uint32_t)__cvta_generic_to_shared(Ks);
    const uint32_t sV = (uint32_t)__cvta_generic_to_shared(Vs);

    const int tid = threadIdx.x;
    const int lane = tid & 31, warp = tid >> 5;
    const int g = lane >> 2, t = lane & 3;
    const int wm = (warp >> 2) * 16;
    const int wni = warp & 3;
    const int wn = wni * 16;
    const int sig = (g >> 1) + ((g & 1) << 2);

    const int tile = blockIdx.x;
    const int p = blockIdx.y;
    const int h = p & 7;
    const int tt = (p >> 3) & 15;
    const int b = p >> 7;
    const size_t rowbase = ((size_t)(b * T_STEPS + tt) * SEQ);
    const float* Qg = g_Q + (rowbase + tile * 64) * 512 + h * HD;
    const float* Kg = g_K + rowbase * 512 + h * HD;
    const float* Vg = g_V + rowbase * 512 + h * HD;
    float*       Cg = g_att + (rowbase + tile * 64) * 512 + h * HD;

    const float alpha = 0.125f * mw[qm[0] * H_NUM + h] * mw[km[0] * H_NUM + h];
    const float sy = tsync[tt * H_NUM + h];

    // ---- prologue: {Q + K0} group, {K1} group ----
#pragma unroll
    for (int i = 0; i < 2; i++) {
        int seg = i * 512 + tid;
        int r = seg >> 4, s = (seg & 15) << 2;
        cpa16(sQ + ((r * FA_QK_W + s) << 2), Qg + (size_t)r * 512 + s);
        cpa16(sK + ((r * FA_QK_W + s) << 2), Kg + (size_t)r * 512 + s);
    }
    cpa_commit();
#pragma unroll
    for (int i = 0; i < 2; i++) {
        int seg = i * 512 + tid;
        int r = seg >> 4, s = (seg & 15) << 2;
        cpa16(sK + ((FA_KBUF + r * FA_QK_W + s) << 2),
              Kg + (size_t)(64 + r) * 512 + s);
    }
    cpa_commit();
    cpa_wait1();
    __syncthreads();

    // ---- preload Q a-fragments (raw: pre-rounded) ----
    uint32_t Qf[8][4];
#pragma unroll
    for (int ks = 0; ks < 8; ks++) {
        const int kc = ks * 8 + t;
        Qf[ks][0] = Qs[(wm + g) * FA_QK_W + kc];
        Qf[ks][1] = Qs[(wm + 8 + g) * FA_QK_W + kc];
        Qf[ks][2] = Qs[(wm + g) * FA_QK_W + kc + 4];
        Qf[ks][3] = Qs[(wm + 8 + g) * FA_QK_W + kc + 4];
    }

    // ---- phase 1: scores into registers ----
    float accS[8][2][4] = {};
#pragma unroll
    for (int c = 0; c < 8; c++) {
        if (c < 7) cpa_wait1(); else cpa_wait0();
        __syncthreads();
        const uint32_t* Kb = Ks + (c & 1) * FA_KBUF;
#pragma unroll
        for (int ks = 0; ks < 8; ks++) {
            const int kc = ks * 8 + t;
#pragma unroll
            for (int kt = 0; kt < 2; kt++) {
                const int n = wn + kt * 8 + sig;
                uint32_t b0 = Kb[n * FA_QK_W + kc];       // raw: pre-rounded
                uint32_t b1 = Kb[n * FA_QK_W + kc + 4];
                mma8(accS[c][kt], Qf[ks], b0, b1);
            }
        }
        __syncthreads();
        if (c + 2 < 8) {
            const int buf = c & 1;
#pragma unroll
            for (int i = 0; i < 2; i++) {
                int seg = i * 512 + tid;
                int r = seg >> 4, s = (seg & 15) << 2;
                cpa16(sK + ((buf * FA_KBUF + r * FA_QK_W + s) << 2),
                      Kg + (size_t)((c + 2) * 64 + r) * 512 + s);
            }
            cpa_commit();
        }
    }

    // ---- prefetch V chunks 0,1 ----
#pragma unroll
    for (int cc = 0; cc < 2; cc++) {
#pragma unroll
        for (int i = 0; i < 2; i++) {
            int seg = i * 512 + tid;
            int r = seg >> 4, s = (seg & 15) << 2;
            cpa16(sV + ((cc * FA_VBUF + r * FA_V_W + s) << 2),
                  Vg + (size_t)(cc * 64 + r) * 512 + s);
        }
        cpa_commit();
    }

    // ---- register softmax ----
    {
        float* aS = &accS[0][0][0];
#pragma unroll
        for (int i = 0; i < 64; i++) aS[i] = aS[i] * alpha + sy;

        float m0 = -1e30f, m1 = -1e30f;
#pragma unroll
        for (int i = 0; i < 64; i += 4) {
            m0 = fmaxf(m0, fmaxf(aS[i], aS[i + 1]));
            m1 = fmaxf(m1, fmaxf(aS[i + 2], aS[i + 3]));
        }
        m0 = fmaxf(m0, __shfl_xor_sync(0xFFFFFFFFu, m0, 1));
        m0 = fmaxf(m0, __shfl_xor_sync(0xFFFFFFFFu, m0, 2));
        m1 = fmaxf(m1, __shfl_xor_sync(0xFFFFFFFFu, m1, 1));
        m1 = fmaxf(m1, __shfl_xor_sync(0xFFFFFFFFu, m1, 2));
        if (t == 0) {
            stats[(wm + g) * 4 + wni] = m0;
            stats[(wm + 8 + g) * 4 + wni] = m1;
        }
        __syncthreads();
        {
            float4 v0 = *(float4*)&stats[(wm + g) * 4];
            m0 = fmaxf(fmaxf(v0.x, v0.y), fmaxf(v0.z, v0.w));
            float4 v1 = *(float4*)&stats[(wm + 8 + g) * 4];
            m1 = fmaxf(fmaxf(v1.x, v1.y), fmaxf(v1.z, v1.w));
        }
        __syncthreads();

        float s0 = 0.f, s1 = 0.f;
#pragma unroll
        for (int i = 0; i < 64; i += 4) {
            float p0 = 1.f / (1.f + __expf(-5.f * (aS[i]     - m0)));
            float p1 = 1.f / (1.f + __expf(-5.f * (aS[i + 1] - m0)));
            float p2 = 1.f / (1.f + __expf(-5.f * (aS[i + 2] - m1)));
            float p3 = 1.f / (1.f + __expf(-5.f * (aS[i + 3] - m1)));
            aS[i] = p0; aS[i + 1] = p1; aS[i + 2] = p2; aS[i + 3] = p3;
            s0 += p0 + p1; s1 += p2 + p3;
        }
        s0 += __shfl_xor_sync(0xFFFFFFFFu, s0, 1);
        s0 += __shfl_xor_sync(0xFFFFFFFFu, s0, 2);
        s1 += __shfl_xor_sync(0xFFFFFFFFu, s1, 1);
        s1 += __shfl_xor_sync(0xFFFFFFFFu, s1, 2);
        if (t == 0) {
            stats[(wm + g) * 4 + wni] = s0;
            stats[(wm + 8 + g) * 4 + wni] = s1;
        }
        __syncthreads();
        {
            float4 v0 = *(float4*)&stats[(wm + g) * 4];
            s0 = v0.x + v0.y + v0.z + v0.w;
            float4 v1 = *(float4*)&stats[(wm + 8 + g) * 4];
            s1 = v1.x + v1.y + v1.z + v1.w;
        }
        const float inv0 = 1.f / (s0 + 1e-8f);
        const float inv1 = 1.f / (s1 + 1e-8f);
#pragma unroll
        for (int i = 0; i < 64; i += 4) {
            aS[i]     = __uint_as_float(f2tf(aS[i]     * inv0));
            aS[i + 1] = __uint_as_float(f2tf(aS[i + 1] * inv0));
            aS[i + 2] = __uint_as_float(f2tf(aS[i + 2] * inv1));
            aS[i + 3] = __uint_as_float(f2tf(aS[i + 3] * inv1));
        }
    }

    // ---- phase 2: partial O over this warp's 128 keys ----
    float acc2[8][4] = {};
#pragma unroll
    for (int c = 0; c < 8; c++) {
        if (c < 7) cpa_wait1(); else cpa_wait0();
        __syncthreads();
        const uint32_t* Vb = Vs + (c & 1) * FA_VBUF;
#pragma unroll
        for (int kt = 0; kt < 2; kt++) {
            uint32_t a[4];
            a[0] = __float_as_uint(accS[c][kt][0]);
            a[1] = __float_as_uint(accS[c][kt][2]);
            a[2] = __float_as_uint(accS[c][kt][1]);
            a[3] = __float_as_uint(accS[c][kt][3]);
            const int klb = wn + kt * 8 + t;
#pragma unroll
            for (int ci = 0; ci < 8; ci++) {
                const int n = ci * 8 + g;
                uint32_t b0 = Vb[klb * FA_V_W + n];       // raw: pre-rounded
                uint32_t b1 = Vb[(klb + 4) * FA_V_W + n];
                mma8(acc2[ci], a, b0, b1);
            }
        }
        __syncthreads();
        if (c + 2 < 8) {
            const int buf = c & 1;
#pragma unroll
            for (int i = 0; i < 2; i++) {
                int seg = i * 512 + tid;
                int r = seg >> 4, s = (seg & 15) << 2;
                cpa16(sV + ((buf * FA_VBUF + r * FA_V_W + s) << 2),
                      Vg + (size_t)((c + 2) * 64 + r) * 512 + s);
            }
            cpa_commit();
        }
    }

    // ---- epilogue: store partials, 4-way reduce, STG ----
    {
        const int opb = warp * 1088;
#pragma unroll
        for (int ci = 0; ci < 8; ci++) {
            float2 v0 = {acc2[ci][0], acc2[ci][1]};
            *(float2*)&Opart[opb + g * FA_QK_W + ci * 8 + 2 * t] = v0;
            float2 v1 = {acc2[ci][2], acc2[ci][3]};
            *(float2*)&Opart[opb + (g + 8) * FA_QK_W + ci * 8 + 2 * t] = v1;
        }
    }
    __syncthreads();
    {
        const int rr = tid >> 3;
        const int c8 = (tid & 7) * 8;
        float4 o0 = {0.f, 0.f, 0.f, 0.f}, o1 = {0.f, 0.f, 0.f, 0.f};
#pragma unroll
        for (int wv = 0; wv < 4; wv++) {
            const float* src = Opart + ((rr >> 4) * 4 + wv) * 1088
                             + (rr & 15) * FA_QK_W + c8;
            float4 x0 = *(const float4*)src;
            float4 x1 = *(const float4*)(src + 4);
            o0.x += x0.x; o0.y += x0.y; o0.z += x0.z; o0.w += x0.w;
            o1.x += x1.x; o1.y += x1.y; o1.z += x1.z; o1.w += x1.w;
        }
        *(float4*)(Cg + (size_t)rr * 512 + c8) = o0;
        *(float4*)(Cg + (size_t)rr * 512 + c8 + 4) = o1;
    }
}

// ============================================================================
// launch
// ============================================================================
#define PJ_SMEM 71680
extern "C" void kernel_launch(void* const* d_in, const int* in_sizes, int n_in,
                              void* d_out, int out_size)
{
    const float* q_sp = (const float*)d_in[0];
    const float* k_sp = (const float*)d_in[1];
    const float* v_sp = (const float*)d_in[2];
    const float* Wq = (const float*)d_in[3];  const float* bq = (const float*)d_in[4];
    const float* Wk = (const float*)d_in[5];  const float* bk = (const float*)d_in[6];
    const float* Wv = (const float*)d_in[7];  const float* bv = (const float*)d_in[8];
    const float* Wo = (const float*)d_in[9];  const float* bo = (const float*)d_in[10];
    const float* mw    = (const float*)d_in[11];
    const float* tsync = (const float*)d_in[12];
    const int* qm = (const int*)d_in[13];
    const int* km = (const int*)d_in[14];
    float* out = (float*)d_out;

    // unconditional (no static guards): idempotent, not stream-ordered
    cudaFuncSetAttribute(proj3_gemm, cudaFuncAttributeMaxDynamicSharedMemorySize, PJ_SMEM);
    cudaFuncSetAttribute(fused_attn, cudaFuncAttributeMaxDynamicSharedMemorySize, FA_SMEM);

    float *dQ, *dK, *dV, *dAtt;
    cudaGetSymbolAddress((void**)&dQ, g_Q);
    cudaGetSymbolAddress((void**)&dK, g_K);
    cudaGetSymbolAddress((void**)&dV, g_V);
    cudaGetSymbolAddress((void**)&dAtt, g_att);

    // Q, K, V projections in one launch (outputs tf32-rounded for fused_attn)
    proj3_gemm<<<dim3(D_EMB / 128, M_ROWS / 128, 3), 256, PJ_SMEM>>>(
        q_sp, Wq, bq, dQ,
        k_sp, Wk, bk, dK,
        v_sp, Wv, bv, dV, 1);

    fused_attn<<<dim3(SEQ / 64, PBATCH), 512, FA_SMEM>>>(mw, tsync, qm, km);

    // output projection (full fp32 output)
    proj3_gemm<<<dim3(D_EMB / 128, M_ROWS / 128, 1), 256, PJ_SMEM>>>(
        dAtt, Wo, bo, out,
        dAtt, Wo, bo, out,
        dAtt, Wo, bo, out, 0);
}